// round 4
// baseline (speedup 1.0000x reference)
#include <cuda_runtime.h>
#include <cuda_bf16.h>
#include <math.h>
#include <stdint.h>

// ---------------- problem constants ----------------
#define BB 2
#define SS 2048
#define HID 5120
#define NH 32
#define DNOPE 128
#define DROPE 64
#define DV 128
#define DQ 192
#define QRANK 1536
#define KVRANK 512
#define MTOK (BB*SS)            // 4096
#define KVAOUT (KVRANK+DROPE)   // 576
#define QBOUT (NH*DQ)           // 6144
#define KVBOUT (NH*(DNOPE+DV))  // 8192

// ---------------- scratch (static device, allocation-free) ----------------
__device__ float g_qc  [(size_t)MTOK*QRANK];
__device__ float g_q   [(size_t)MTOK*QBOUT];
__device__ float g_ckv [(size_t)MTOK*KVAOUT];
__device__ float g_cn  [(size_t)MTOK*KVRANK];
__device__ float g_kv  [(size_t)MTOK*KVBOUT];
__device__ float g_Qh  [(size_t)BB*NH*SS*DQ];
__device__ float g_Kh  [(size_t)BB*NH*SS*DQ];
__device__ float g_Vh  [(size_t)BB*NH*SS*DV];
__device__ float g_attn[(size_t)MTOK*(NH*DV)];

// ---------------- tiled SGEMM (projections only) ----------------
// C[m,n] = sum_k A[m,k] * B'[k,n];  BT=true: B stored [N,K] (B'=B^T)
#define BM 64
#define BN 64
#define BK 16

template<bool BT>
__global__ __launch_bounds__(256)
void gemm_k(const float* __restrict__ A, const float* __restrict__ B,
            float* __restrict__ C,
            int M, int N, int K, int lda, int ldb, int ldc)
{
    const int m0 = blockIdx.y * BM;
    const int n0 = blockIdx.x * BN;

    __shared__ float As[BK][BM];
    __shared__ float Bs[BK][BN];

    const int tid = threadIdx.x;           // 256 threads
    const int tx  = tid & 15;
    const int ty  = tid >> 4;
    const int lr  = tid >> 2;              // 0..63
    const int lc  = (tid & 3) * 4;         // 0,4,8,12
    const int r16 = tid >> 4;              // 0..15
    const int c16 = (tid & 15) * 4;        // 0..60

    float acc[4][4] = {};

    for (int k0 = 0; k0 < K; k0 += BK) {
        float4 av = *reinterpret_cast<const float4*>(&A[(size_t)(m0 + lr) * lda + k0 + lc]);
        As[lc + 0][lr] = av.x; As[lc + 1][lr] = av.y;
        As[lc + 2][lr] = av.z; As[lc + 3][lr] = av.w;
        if (BT) {
            float4 bv = *reinterpret_cast<const float4*>(&B[(size_t)(n0 + lr) * ldb + k0 + lc]);
            Bs[lc + 0][lr] = bv.x; Bs[lc + 1][lr] = bv.y;
            Bs[lc + 2][lr] = bv.z; Bs[lc + 3][lr] = bv.w;
        } else {
            float4 bv = *reinterpret_cast<const float4*>(&B[(size_t)(k0 + r16) * ldb + n0 + c16]);
            *reinterpret_cast<float4*>(&Bs[r16][c16]) = bv;
        }
        __syncthreads();

        #pragma unroll
        for (int kk = 0; kk < BK; kk++) {
            float4 a4 = *reinterpret_cast<const float4*>(&As[kk][ty * 4]);
            float4 b4 = *reinterpret_cast<const float4*>(&Bs[kk][tx * 4]);
            float af[4] = {a4.x, a4.y, a4.z, a4.w};
            float bf[4] = {b4.x, b4.y, b4.z, b4.w};
            #pragma unroll
            for (int i = 0; i < 4; i++)
                #pragma unroll
                for (int j = 0; j < 4; j++)
                    acc[i][j] += af[i] * bf[j];
        }
        __syncthreads();
    }

    #pragma unroll
    for (int i = 0; i < 4; i++) {
        float4 cv = make_float4(acc[i][0], acc[i][1], acc[i][2], acc[i][3]);
        *reinterpret_cast<float4*>(&C[(size_t)(m0 + ty * 4 + i) * ldc + n0 + tx * 4]) = cv;
    }
}

// ---------------- RMSNorm (row-wise) ----------------
__global__ __launch_bounds__(256)
void rmsnorm_k(const float* __restrict__ x, const float* __restrict__ w,
               float* __restrict__ y, int n, int in_stride, int out_stride)
{
    const int row = blockIdx.x;
    const float* xr = x + (size_t)row * in_stride;
    float* yr = y + (size_t)row * out_stride;
    __shared__ float red[256];
    float s = 0.f;
    for (int i = threadIdx.x; i < n; i += 256) { float v = xr[i]; s += v * v; }
    red[threadIdx.x] = s; __syncthreads();
    for (int o = 128; o; o >>= 1) {
        if (threadIdx.x < o) red[threadIdx.x] += red[threadIdx.x + o];
        __syncthreads();
    }
    const float r = rsqrtf(red[0] / n + 1e-6f);
    for (int i = threadIdx.x; i < n; i += 256) yr[i] = xr[i] * r * w[i];
}

// ---------------- build Q with RoPE: [tok, h*192] -> [b,h,s,192] ----------------
__global__ __launch_bounds__(128)
void build_q_k(const float* __restrict__ q, const int* __restrict__ pos,
               float* __restrict__ Qh)
{
    const int s = blockIdx.x, h = blockIdx.y, b = blockIdx.z;
    const float* in = q + ((size_t)(b * SS + s)) * QBOUT + h * DQ;
    float* out = Qh + (((size_t)(b * NH + h) * SS) + s) * DQ;
    const int t = threadIdx.x;
    out[t] = in[t];                       // nope part (t covers 0..127)
    if (t < 32) {
        const float tp = (float)pos[b * SS + s];
        // inv_freq = 10000^(-t/32) = exp2(-t/32 * log2(10000)); accurate trig for large phase
        const float f = exp2f((float)t * (-13.2877123795494f / 32.f));
        float c, sn; sincosf(tp * f, &sn, &c);
        const float x0 = in[DNOPE + 2 * t];
        const float x1 = in[DNOPE + 2 * t + 1];
        out[DNOPE + t]      = x0 * c - x1 * sn;
        out[DNOPE + 32 + t] = x1 * c + x0 * sn;
    }
}

// ---------------- build K,V: kv[tok,h*256] + roped k_pe -> [b,h,s,*] ----------------
__global__ __launch_bounds__(256)
void build_kv_k(const float* __restrict__ ckv, const float* __restrict__ kv,
                const int* __restrict__ pos,
                float* __restrict__ Kh, float* __restrict__ Vh)
{
    const int s = blockIdx.x, b = blockIdx.y;
    const size_t bs = (size_t)b * SS + s;
    __shared__ float kr[DROPE];
    const int tid = threadIdx.x;
    if (tid < 32) {
        const float tp = (float)pos[bs];
        const float f = exp2f((float)tid * (-13.2877123795494f / 32.f));
        float c, sn; sincosf(tp * f, &sn, &c);
        const float x0 = ckv[bs * KVAOUT + KVRANK + 2 * tid];
        const float x1 = ckv[bs * KVAOUT + KVRANK + 2 * tid + 1];
        kr[tid]      = x0 * c - x1 * sn;
        kr[32 + tid] = x1 * c + x0 * sn;
    }
    __syncthreads();
    const float* kvrow = kv + bs * KVBOUT;
    for (int idx = tid; idx < NH * DQ; idx += 256) {
        const int h = idx / DQ, d = idx % DQ;
        const float v = (d < DNOPE) ? kvrow[h * (DNOPE + DV) + d] : kr[d - DNOPE];
        Kh[(((size_t)(b * NH + h) * SS) + s) * DQ + d] = v;
    }
    for (int idx = tid; idx < NH * DV; idx += 256) {
        const int h = idx / DV, d = idx % DV;
        Vh[(((size_t)(b * NH + h) * SS) + s) * DV + d] = kvrow[h * (DNOPE + DV) + DNOPE + d];
    }
}

// ---------------- fused flash attention (causal, online softmax) ----------------
// One CTA = one (b,h) x 64 q-rows. Tiles of 64 keys. No materialized scores.
#define FM 64
#define FN 64
#define FLASH_SMEM ((DQ*FM + DQ*FN + FN*DV + FM*FN) * 4)   // 147456 bytes

__global__ __launch_bounds__(256)
void flash_k(const float* __restrict__ Qh, const float* __restrict__ Kh,
             const float* __restrict__ Vh, float* __restrict__ attn, float scale)
{
    extern __shared__ float smf[];
    float* Qs = smf;                    // [DQ][FM]  (k-major / transposed)
    float* Ks = Qs + DQ * FM;           // [DQ][FN]
    float* Vs = Ks + DQ * FN;           // [FN][DV]
    float* Ps = Vs + FN * DV;           // [FM][FN]

    const int qt = blockIdx.x;
    const int bh = blockIdx.y;
    const int b  = bh / NH, h = bh % NH;
    const int q0 = qt * FM;
    const int tid = threadIdx.x;
    const int tx = tid & 15, ty = tid >> 4;

    const float* Qg = Qh + ((size_t)bh * SS + q0) * DQ;
    const float* Kg = Kh + (size_t)bh * SS * DQ;
    const float* Vg = Vh + (size_t)bh * SS * DV;

    // Q tile -> transposed smem, pre-scaled
    for (int idx = tid; idx < FM * (DQ / 4); idx += 256) {
        const int row = idx / (DQ / 4);
        const int d4  = (idx % (DQ / 4)) * 4;
        float4 v = *reinterpret_cast<const float4*>(&Qg[(size_t)row * DQ + d4]);
        Qs[(d4 + 0) * FM + row] = v.x * scale;
        Qs[(d4 + 1) * FM + row] = v.y * scale;
        Qs[(d4 + 2) * FM + row] = v.z * scale;
        Qs[(d4 + 3) * FM + row] = v.w * scale;
    }

    float o[4][8];
    #pragma unroll
    for (int i = 0; i < 4; i++)
        #pragma unroll
        for (int j = 0; j < 8; j++) o[i][j] = 0.f;
    float mrow[4] = {-1e30f, -1e30f, -1e30f, -1e30f};
    float lrow[4] = {0.f, 0.f, 0.f, 0.f};

    for (int kt = 0; kt <= qt; kt++) {
        const int k0 = kt * FN;
        __syncthreads();    // prev-iter consumers of Ks/Vs/Ps done (also covers Q load, iter 0)

        for (int idx = tid; idx < FN * (DQ / 4); idx += 256) {
            const int row = idx / (DQ / 4);
            const int d4  = (idx % (DQ / 4)) * 4;
            float4 v = *reinterpret_cast<const float4*>(&Kg[(size_t)(k0 + row) * DQ + d4]);
            Ks[(d4 + 0) * FN + row] = v.x;
            Ks[(d4 + 1) * FN + row] = v.y;
            Ks[(d4 + 2) * FN + row] = v.z;
            Ks[(d4 + 3) * FN + row] = v.w;
        }
        for (int idx = tid; idx < FN * DV / 4; idx += 256) {
            *reinterpret_cast<float4*>(&Vs[idx * 4]) =
                *reinterpret_cast<const float4*>(&Vg[(size_t)k0 * DV + idx * 4]);
        }
        __syncthreads();

        // S = (Q*scale) @ K^T : 4x4 per thread
        float s[4][4] = {};
        #pragma unroll 4
        for (int kk = 0; kk < DQ; kk++) {
            float4 qv = *reinterpret_cast<const float4*>(&Qs[kk * FM + ty * 4]);
            float4 kv = *reinterpret_cast<const float4*>(&Ks[kk * FN + tx * 4]);
            float qa[4] = {qv.x, qv.y, qv.z, qv.w};
            float ka[4] = {kv.x, kv.y, kv.z, kv.w};
            #pragma unroll
            for (int i = 0; i < 4; i++)
                #pragma unroll
                for (int j = 0; j < 4; j++)
                    s[i][j] += qa[i] * ka[j];
        }

        if (kt == qt) {   // diagonal tile: causal mask (k0 == q0)
            #pragma unroll
            for (int i = 0; i < 4; i++)
                #pragma unroll
                for (int j = 0; j < 4; j++)
                    if (tx * 4 + j > ty * 4 + i) s[i][j] = -1e30f;
        }

        float alpha[4];
        #pragma unroll
        for (int i = 0; i < 4; i++) {
            float tm = fmaxf(fmaxf(s[i][0], s[i][1]), fmaxf(s[i][2], s[i][3]));
            #pragma unroll
            for (int w = 1; w < 16; w <<= 1)
                tm = fmaxf(tm, __shfl_xor_sync(0xffffffffu, tm, w));
            const float mn = fmaxf(mrow[i], tm);
            alpha[i] = __expf(mrow[i] - mn);
            float rs = 0.f;
            #pragma unroll
            for (int j = 0; j < 4; j++) { s[i][j] = __expf(s[i][j] - mn); rs += s[i][j]; }
            #pragma unroll
            for (int w = 1; w < 16; w <<= 1)
                rs += __shfl_xor_sync(0xffffffffu, rs, w);
            lrow[i] = lrow[i] * alpha[i] + rs;
            mrow[i] = mn;
            *reinterpret_cast<float4*>(&Ps[(ty * 4 + i) * FN + tx * 4]) =
                make_float4(s[i][0], s[i][1], s[i][2], s[i][3]);
        }
        __syncthreads();

        // O = O*alpha + P @ V   (thread cols: tx*4..+3 and 64+tx*4..+3)
        #pragma unroll
        for (int i = 0; i < 4; i++)
            #pragma unroll
            for (int j = 0; j < 8; j++) o[i][j] *= alpha[i];
        #pragma unroll 2
        for (int kk = 0; kk < FN; kk++) {
            float4 va = *reinterpret_cast<const float4*>(&Vs[kk * DV + tx * 4]);
            float4 vb = *reinterpret_cast<const float4*>(&Vs[kk * DV + 64 + tx * 4]);
            #pragma unroll
            for (int i = 0; i < 4; i++) {
                const float p = Ps[(ty * 4 + i) * FN + kk];
                o[i][0] += p * va.x; o[i][1] += p * va.y;
                o[i][2] += p * va.z; o[i][3] += p * va.w;
                o[i][4] += p * vb.x; o[i][5] += p * vb.y;
                o[i][6] += p * vb.z; o[i][7] += p * vb.w;
            }
        }
    }

    // epilogue: normalize, write [tok, h*128]
    #pragma unroll
    for (int i = 0; i < 4; i++) {
        const float inv = 1.f / lrow[i];
        const int r = q0 + ty * 4 + i;
        float* dst = attn + ((size_t)(b * SS + r)) * (NH * DV) + h * DV;
        *reinterpret_cast<float4*>(&dst[tx * 4]) =
            make_float4(o[i][0] * inv, o[i][1] * inv, o[i][2] * inv, o[i][3] * inv);
        *reinterpret_cast<float4*>(&dst[64 + tx * 4]) =
            make_float4(o[i][4] * inv, o[i][5] * inv, o[i][6] * inv, o[i][7] * inv);
    }
}

// ---------------- launch ----------------
extern "C" void kernel_launch(void* const* d_in, const int* in_sizes, int n_in,
                              void* d_out, int out_size)
{
    const float* hidden = (const float*)d_in[0];
    const float* qaw    = (const float*)d_in[1];
    const float* qaln   = (const float*)d_in[2];
    const float* qbw    = (const float*)d_in[3];
    const float* kvaw   = (const float*)d_in[4];
    const float* kvaln  = (const float*)d_in[5];
    const float* kvbw   = (const float*)d_in[6];
    const float* ow     = (const float*)d_in[7];
    const int*   pos    = (const int*)d_in[8];
    // d_in[9] = attention_mask (causal tril) — enforced analytically in flash kernel
    float* out = (float*)d_out;

    float* qc = nullptr;  cudaGetSymbolAddress((void**)&qc,  g_qc);
    float* q  = nullptr;  cudaGetSymbolAddress((void**)&q,   g_q);
    float* ckv= nullptr;  cudaGetSymbolAddress((void**)&ckv, g_ckv);
    float* cn = nullptr;  cudaGetSymbolAddress((void**)&cn,  g_cn);
    float* kv = nullptr;  cudaGetSymbolAddress((void**)&kv,  g_kv);
    float* Qh = nullptr;  cudaGetSymbolAddress((void**)&Qh,  g_Qh);
    float* Kh = nullptr;  cudaGetSymbolAddress((void**)&Kh,  g_Kh);
    float* Vh = nullptr;  cudaGetSymbolAddress((void**)&Vh,  g_Vh);
    float* at = nullptr;  cudaGetSymbolAddress((void**)&at,  g_attn);

    cudaFuncSetAttribute(flash_k, cudaFuncAttributeMaxDynamicSharedMemorySize, FLASH_SMEM);

    // 1) q_c = hidden @ q_a^T   [4096,1536]
    gemm_k<true><<<dim3(QRANK/BN, MTOK/BM), 256>>>(
        hidden, qaw, qc, MTOK, QRANK, HID, HID, HID, QRANK);
    // 2) rmsnorm q_c (in place)
    rmsnorm_k<<<MTOK, 256>>>(qc, qaln, qc, QRANK, QRANK, QRANK);
    // 3) q = qcn @ q_b^T        [4096,6144]
    gemm_k<true><<<dim3(QBOUT/BN, MTOK/BM), 256>>>(
        qc, qbw, q, MTOK, QBOUT, QRANK, QRANK, QRANK, QBOUT);
    // 4) ckv = hidden @ kv_a^T  [4096,576]
    gemm_k<true><<<dim3(KVAOUT/BN, MTOK/BM), 256>>>(
        hidden, kvaw, ckv, MTOK, KVAOUT, HID, HID, HID, KVAOUT);
    // 5) rmsnorm first 512 -> cn
    rmsnorm_k<<<MTOK, 256>>>(ckv, kvaln, cn, KVRANK, KVAOUT, KVRANK);
    // 6) kv = cn @ kv_b^T       [4096,8192]
    gemm_k<true><<<dim3(KVBOUT/BN, MTOK/BM), 256>>>(
        cn, kvbw, kv, MTOK, KVBOUT, KVRANK, KVRANK, KVRANK, KVBOUT);
    // 7) build Q (rope) and K,V layouts
    build_q_k<<<dim3(SS, NH, BB), 128>>>(q, pos, Qh);
    build_kv_k<<<dim3(SS, BB), 256>>>(ckv, kv, pos, Kh, Vh);
    // 8) fused causal flash attention -> attn [tok, h*128]
    flash_k<<<dim3(SS/FM, BB*NH), 256, FLASH_SMEM>>>(
        Qh, Kh, Vh, at, rsqrtf((float)DQ));
    // 9) out = attn @ o^T       [4096,5120]
    gemm_k<true><<<dim3(HID/BN, MTOK/BM), 256>>>(
        at, ow, out, MTOK, HID, NH*DV, NH*DV, NH*DV, HID);
}

// round 6
// speedup vs baseline: 1.3056x; 1.3056x over previous
#include <cuda_runtime.h>
#include <cuda_bf16.h>
#include <math.h>
#include <stdint.h>

// ---------------- problem constants ----------------
#define BB 2
#define SS 2048
#define HID 5120
#define NH 32
#define DNOPE 128
#define DROPE 64
#define DV 128
#define DQ 192
#define QRANK 1536
#define KVRANK 512
#define MTOK (BB*SS)            // 4096
#define KVAOUT (KVRANK+DROPE)   // 576
#define QBOUT (NH*DQ)           // 6144
#define KVBOUT (NH*(DNOPE+DV))  // 8192

// ---------------- scratch (static device, allocation-free) ----------------
__device__ float g_qc  [(size_t)MTOK*QRANK];
__device__ float g_q   [(size_t)MTOK*QBOUT];
__device__ float g_ckv [(size_t)MTOK*KVAOUT];
__device__ float g_cn  [(size_t)MTOK*KVRANK];
__device__ float g_kv  [(size_t)MTOK*KVBOUT];
__device__ float g_Qh  [(size_t)BB*NH*SS*DQ];
__device__ float g_Kh  [(size_t)BB*NH*SS*DQ];
__device__ float g_Vh  [(size_t)BB*NH*SS*DV];
__device__ float g_attn[(size_t)MTOK*(NH*DV)];

// ================= 128x128 SGEMM, 8x8 split microtile, NT =================
// C[m,n] = sum_k A[m,k] * B[n,k]   (A:[M,K] rm, B:[N,K] rm, C:[M,N] rm)
// Requires M%128==0, N%128==0, K%8==0.
#define GM 128
#define GN 128
#define GK 8

__global__ __launch_bounds__(256)
void gemm128_k(const float* __restrict__ A, const float* __restrict__ B,
               float* __restrict__ C, int K, int lda, int ldb, int ldc)
{
    __shared__ float As[GK][GM];
    __shared__ float Bs[GK][GN];

    const int tid = threadIdx.x;
    const int m0 = blockIdx.y * GM;
    const int n0 = blockIdx.x * GN;

    // global-load mapping: thread -> (row = tid/2, kc = (tid&1)*4)
    const int lr = tid >> 1;           // 0..127
    const int lc = (tid & 1) * 4;      // 0 or 4

    // compute mapping (split 8x8): rows {ty*4+i, 64+ty*4+i}, cols {tx*4+j, 64+tx*4+j}
    const int tx = tid & 15;
    const int ty = tid >> 4;

    const float* Ag = A + (size_t)(m0 + lr) * lda + lc;
    const float* Bg = B + (size_t)(n0 + lr) * ldb + lc;

    float4 aN = *reinterpret_cast<const float4*>(Ag);
    float4 bN = *reinterpret_cast<const float4*>(Bg);

    float acc[8][8];
    #pragma unroll
    for (int i = 0; i < 8; i++)
        #pragma unroll
        for (int j = 0; j < 8; j++) acc[i][j] = 0.f;

    for (int k0 = 0; k0 < K; k0 += GK) {
        // stash prefetched tile (transposed: As[k][m])
        As[lc + 0][lr] = aN.x; As[lc + 1][lr] = aN.y;
        As[lc + 2][lr] = aN.z; As[lc + 3][lr] = aN.w;
        Bs[lc + 0][lr] = bN.x; Bs[lc + 1][lr] = bN.y;
        Bs[lc + 2][lr] = bN.z; Bs[lc + 3][lr] = bN.w;
        __syncthreads();

        if (k0 + GK < K) {   // prefetch next tile during compute
            aN = *reinterpret_cast<const float4*>(Ag + k0 + GK);
            bN = *reinterpret_cast<const float4*>(Bg + k0 + GK);
        }

        #pragma unroll
        for (int kk = 0; kk < GK; kk++) {
            float4 a0 = *reinterpret_cast<const float4*>(&As[kk][ty * 4]);
            float4 a1 = *reinterpret_cast<const float4*>(&As[kk][64 + ty * 4]);
            float4 b0 = *reinterpret_cast<const float4*>(&Bs[kk][tx * 4]);
            float4 b1 = *reinterpret_cast<const float4*>(&Bs[kk][64 + tx * 4]);
            float af[8] = {a0.x, a0.y, a0.z, a0.w, a1.x, a1.y, a1.z, a1.w};
            float bf[8] = {b0.x, b0.y, b0.z, b0.w, b1.x, b1.y, b1.z, b1.w};
            #pragma unroll
            for (int i = 0; i < 8; i++)
                #pragma unroll
                for (int j = 0; j < 8; j++)
                    acc[i][j] += af[i] * bf[j];
        }
        __syncthreads();
    }

    #pragma unroll
    for (int ih = 0; ih < 2; ih++)
        #pragma unroll
        for (int i = 0; i < 4; i++) {
            const int r = m0 + ih * 64 + ty * 4 + i;
            float* Cr = C + (size_t)r * ldc + n0;
            *reinterpret_cast<float4*>(&Cr[tx * 4]) =
                make_float4(acc[ih*4+i][0], acc[ih*4+i][1], acc[ih*4+i][2], acc[ih*4+i][3]);
            *reinterpret_cast<float4*>(&Cr[64 + tx * 4]) =
                make_float4(acc[ih*4+i][4], acc[ih*4+i][5], acc[ih*4+i][6], acc[ih*4+i][7]);
        }
}

// ================= 64x64 SGEMM (kv_a only: N=576) =================
#define BM 64
#define BN 64
#define BK 16

__global__ __launch_bounds__(256)
void gemm64_k(const float* __restrict__ A, const float* __restrict__ B,
              float* __restrict__ C, int K, int lda, int ldb, int ldc)
{
    const int m0 = blockIdx.y * BM;
    const int n0 = blockIdx.x * BN;

    __shared__ float As[BK][BM];
    __shared__ float Bs[BK][BN];

    const int tid = threadIdx.x;
    const int tx  = tid & 15;
    const int ty  = tid >> 4;
    const int lr  = tid >> 2;
    const int lc  = (tid & 3) * 4;

    float acc[4][4] = {};

    for (int k0 = 0; k0 < K; k0 += BK) {
        float4 av = *reinterpret_cast<const float4*>(&A[(size_t)(m0 + lr) * lda + k0 + lc]);
        As[lc + 0][lr] = av.x; As[lc + 1][lr] = av.y;
        As[lc + 2][lr] = av.z; As[lc + 3][lr] = av.w;
        float4 bv = *reinterpret_cast<const float4*>(&B[(size_t)(n0 + lr) * ldb + k0 + lc]);
        Bs[lc + 0][lr] = bv.x; Bs[lc + 1][lr] = bv.y;
        Bs[lc + 2][lr] = bv.z; Bs[lc + 3][lr] = bv.w;
        __syncthreads();

        #pragma unroll
        for (int kk = 0; kk < BK; kk++) {
            float4 a4 = *reinterpret_cast<const float4*>(&As[kk][ty * 4]);
            float4 b4 = *reinterpret_cast<const float4*>(&Bs[kk][tx * 4]);
            float af[4] = {a4.x, a4.y, a4.z, a4.w};
            float bf[4] = {b4.x, b4.y, b4.z, b4.w};
            #pragma unroll
            for (int i = 0; i < 4; i++)
                #pragma unroll
                for (int j = 0; j < 4; j++)
                    acc[i][j] += af[i] * bf[j];
        }
        __syncthreads();
    }

    #pragma unroll
    for (int i = 0; i < 4; i++) {
        float4 cv = make_float4(acc[i][0], acc[i][1], acc[i][2], acc[i][3]);
        *reinterpret_cast<float4*>(&C[(size_t)(m0 + ty * 4 + i) * ldc + n0 + tx * 4]) = cv;
    }
}

// ---------------- RMSNorm (row-wise) ----------------
__global__ __launch_bounds__(256)
void rmsnorm_k(const float* __restrict__ x, const float* __restrict__ w,
               float* __restrict__ y, int n, int in_stride, int out_stride)
{
    const int row = blockIdx.x;
    const float* xr = x + (size_t)row * in_stride;
    float* yr = y + (size_t)row * out_stride;
    __shared__ float red[256];
    float s = 0.f;
    for (int i = threadIdx.x; i < n; i += 256) { float v = xr[i]; s += v * v; }
    red[threadIdx.x] = s; __syncthreads();
    for (int o = 128; o; o >>= 1) {
        if (threadIdx.x < o) red[threadIdx.x] += red[threadIdx.x + o];
        __syncthreads();
    }
    const float r = rsqrtf(red[0] / n + 1e-6f);
    for (int i = threadIdx.x; i < n; i += 256) yr[i] = xr[i] * r * w[i];
}

// ---------------- build Q with RoPE: [tok, h*192] -> [b,h,s,192] ----------------
__global__ __launch_bounds__(128)
void build_q_k(const float* __restrict__ q, const int* __restrict__ pos,
               float* __restrict__ Qh)
{
    const int s = blockIdx.x, h = blockIdx.y, b = blockIdx.z;
    const float* in = q + ((size_t)(b * SS + s)) * QBOUT + h * DQ;
    float* out = Qh + (((size_t)(b * NH + h) * SS) + s) * DQ;
    const int t = threadIdx.x;
    out[t] = in[t];
    if (t < 32) {
        const float tp = (float)pos[b * SS + s];
        const float f = exp2f((float)t * (-13.2877123795494f / 32.f));
        float c, sn; sincosf(tp * f, &sn, &c);
        const float x0 = in[DNOPE + 2 * t];
        const float x1 = in[DNOPE + 2 * t + 1];
        out[DNOPE + t]      = x0 * c - x1 * sn;
        out[DNOPE + 32 + t] = x1 * c + x0 * sn;
    }
}

// ---------------- build K,V ----------------
__global__ __launch_bounds__(256)
void build_kv_k(const float* __restrict__ ckv, const float* __restrict__ kv,
                const int* __restrict__ pos,
                float* __restrict__ Kh, float* __restrict__ Vh)
{
    const int s = blockIdx.x, b = blockIdx.y;
    const size_t bs = (size_t)b * SS + s;
    __shared__ float kr[DROPE];
    const int tid = threadIdx.x;
    if (tid < 32) {
        const float tp = (float)pos[bs];
        const float f = exp2f((float)tid * (-13.2877123795494f / 32.f));
        float c, sn; sincosf(tp * f, &sn, &c);
        const float x0 = ckv[bs * KVAOUT + KVRANK + 2 * tid];
        const float x1 = ckv[bs * KVAOUT + KVRANK + 2 * tid + 1];
        kr[tid]      = x0 * c - x1 * sn;
        kr[32 + tid] = x1 * c + x0 * sn;
    }
    __syncthreads();
    const float* kvrow = kv + bs * KVBOUT;
    for (int idx = tid; idx < NH * DQ; idx += 256) {
        const int h = idx / DQ, d = idx % DQ;
        const float v = (d < DNOPE) ? kvrow[h * (DNOPE + DV) + d] : kr[d - DNOPE];
        Kh[(((size_t)(b * NH + h) * SS) + s) * DQ + d] = v;
    }
    for (int idx = tid; idx < NH * DV; idx += 256) {
        const int h = idx / DV, d = idx % DV;
        Vh[(((size_t)(b * NH + h) * SS) + s) * DV + d] = kvrow[h * (DNOPE + DV) + DNOPE + d];
    }
}

// ---------------- fused flash attention (causal, online softmax) ----------------
#define FM 64
#define FN 64
#define FLASH_SMEM ((DQ*FM + DQ*FN + FN*DV + FM*FN) * 4)   // 147456 bytes

__global__ __launch_bounds__(256)
void flash_k(const float* __restrict__ Qh, const float* __restrict__ Kh,
             const float* __restrict__ Vh, float* __restrict__ attn, float scale)
{
    extern __shared__ float smf[];
    float* Qs = smf;                    // [DQ][FM]
    float* Ks = Qs + DQ * FM;           // [DQ][FN]
    float* Vs = Ks + DQ * FN;           // [FN][DV]
    float* Ps = Vs + FN * DV;           // [FM][FN]

    const int qt = blockIdx.x;
    const int bh = blockIdx.y;
    const int b  = bh / NH, h = bh % NH;
    const int q0 = qt * FM;
    const int tid = threadIdx.x;
    const int tx = tid & 15, ty = tid >> 4;

    const float* Qg = Qh + ((size_t)bh * SS + q0) * DQ;
    const float* Kg = Kh + (size_t)bh * SS * DQ;
    const float* Vg = Vh + (size_t)bh * SS * DV;

    for (int idx = tid; idx < FM * (DQ / 4); idx += 256) {
        const int row = idx / (DQ / 4);
        const int d4  = (idx % (DQ / 4)) * 4;
        float4 v = *reinterpret_cast<const float4*>(&Qg[(size_t)row * DQ + d4]);
        Qs[(d4 + 0) * FM + row] = v.x * scale;
        Qs[(d4 + 1) * FM + row] = v.y * scale;
        Qs[(d4 + 2) * FM + row] = v.z * scale;
        Qs[(d4 + 3) * FM + row] = v.w * scale;
    }

    float o[4][8];
    #pragma unroll
    for (int i = 0; i < 4; i++)
        #pragma unroll
        for (int j = 0; j < 8; j++) o[i][j] = 0.f;
    float mrow[4] = {-1e30f, -1e30f, -1e30f, -1e30f};
    float lrow[4] = {0.f, 0.f, 0.f, 0.f};

    for (int kt = 0; kt <= qt; kt++) {
        const int k0 = kt * FN;
        __syncthreads();

        for (int idx = tid; idx < FN * (DQ / 4); idx += 256) {
            const int row = idx / (DQ / 4);
            const int d4  = (idx % (DQ / 4)) * 4;
            float4 v = *reinterpret_cast<const float4*>(&Kg[(size_t)(k0 + row) * DQ + d4]);
            Ks[(d4 + 0) * FN + row] = v.x;
            Ks[(d4 + 1) * FN + row] = v.y;
            Ks[(d4 + 2) * FN + row] = v.z;
            Ks[(d4 + 3) * FN + row] = v.w;
        }
        for (int idx = tid; idx < FN * DV / 4; idx += 256) {
            *reinterpret_cast<float4*>(&Vs[idx * 4]) =
                *reinterpret_cast<const float4*>(&Vg[(size_t)k0 * DV + idx * 4]);
        }
        __syncthreads();

        float s[4][4] = {};
        #pragma unroll 4
        for (int kk = 0; kk < DQ; kk++) {
            float4 qv = *reinterpret_cast<const float4*>(&Qs[kk * FM + ty * 4]);
            float4 kv = *reinterpret_cast<const float4*>(&Ks[kk * FN + tx * 4]);
            float qa[4] = {qv.x, qv.y, qv.z, qv.w};
            float ka[4] = {kv.x, kv.y, kv.z, kv.w};
            #pragma unroll
            for (int i = 0; i < 4; i++)
                #pragma unroll
                for (int j = 0; j < 4; j++)
                    s[i][j] += qa[i] * ka[j];
        }

        if (kt == qt) {
            #pragma unroll
            for (int i = 0; i < 4; i++)
                #pragma unroll
                for (int j = 0; j < 4; j++)
                    if (tx * 4 + j > ty * 4 + i) s[i][j] = -1e30f;
        }

        float alpha[4];
        #pragma unroll
        for (int i = 0; i < 4; i++) {
            float tm = fmaxf(fmaxf(s[i][0], s[i][1]), fmaxf(s[i][2], s[i][3]));
            #pragma unroll
            for (int w = 1; w < 16; w <<= 1)
                tm = fmaxf(tm, __shfl_xor_sync(0xffffffffu, tm, w));
            const float mn = fmaxf(mrow[i], tm);
            alpha[i] = __expf(mrow[i] - mn);
            float rs = 0.f;
            #pragma unroll
            for (int j = 0; j < 4; j++) { s[i][j] = __expf(s[i][j] - mn); rs += s[i][j]; }
            #pragma unroll
            for (int w = 1; w < 16; w <<= 1)
                rs += __shfl_xor_sync(0xffffffffu, rs, w);
            lrow[i] = lrow[i] * alpha[i] + rs;
            mrow[i] = mn;
            *reinterpret_cast<float4*>(&Ps[(ty * 4 + i) * FN + tx * 4]) =
                make_float4(s[i][0], s[i][1], s[i][2], s[i][3]);
        }
        __syncthreads();

        #pragma unroll
        for (int i = 0; i < 4; i++)
            #pragma unroll
            for (int j = 0; j < 8; j++) o[i][j] *= alpha[i];
        #pragma unroll 2
        for (int kk = 0; kk < FN; kk++) {
            float4 va = *reinterpret_cast<const float4*>(&Vs[kk * DV + tx * 4]);
            float4 vb = *reinterpret_cast<const float4*>(&Vs[kk * DV + 64 + tx * 4]);
            #pragma unroll
            for (int i = 0; i < 4; i++) {
                const float p = Ps[(ty * 4 + i) * FN + kk];
                o[i][0] += p * va.x; o[i][1] += p * va.y;
                o[i][2] += p * va.z; o[i][3] += p * va.w;
                o[i][4] += p * vb.x; o[i][5] += p * vb.y;
                o[i][6] += p * vb.z; o[i][7] += p * vb.w;
            }
        }
    }

    #pragma unroll
    for (int i = 0; i < 4; i++) {
        const float inv = 1.f / lrow[i];
        const int r = q0 + ty * 4 + i;
        float* dst = attn + ((size_t)(b * SS + r)) * (NH * DV) + h * DV;
        *reinterpret_cast<float4*>(&dst[tx * 4]) =
            make_float4(o[i][0] * inv, o[i][1] * inv, o[i][2] * inv, o[i][3] * inv);
        *reinterpret_cast<float4*>(&dst[64 + tx * 4]) =
            make_float4(o[i][4] * inv, o[i][5] * inv, o[i][6] * inv, o[i][7] * inv);
    }
}

// ---------------- launch ----------------
extern "C" void kernel_launch(void* const* d_in, const int* in_sizes, int n_in,
                              void* d_out, int out_size)
{
    const float* hidden = (const float*)d_in[0];
    const float* qaw    = (const float*)d_in[1];
    const float* qaln   = (const float*)d_in[2];
    const float* qbw    = (const float*)d_in[3];
    const float* kvaw   = (const float*)d_in[4];
    const float* kvaln  = (const float*)d_in[5];
    const float* kvbw   = (const float*)d_in[6];
    const float* ow     = (const float*)d_in[7];
    const int*   pos    = (const int*)d_in[8];
    // d_in[9] = attention_mask (causal tril) — enforced analytically in flash kernel
    float* out = (float*)d_out;

    float* qc = nullptr;  cudaGetSymbolAddress((void**)&qc,  g_qc);
    float* q  = nullptr;  cudaGetSymbolAddress((void**)&q,   g_q);
    float* ckv= nullptr;  cudaGetSymbolAddress((void**)&ckv, g_ckv);
    float* cn = nullptr;  cudaGetSymbolAddress((void**)&cn,  g_cn);
    float* kv = nullptr;  cudaGetSymbolAddress((void**)&kv,  g_kv);
    float* Qh = nullptr;  cudaGetSymbolAddress((void**)&Qh,  g_Qh);
    float* Kh = nullptr;  cudaGetSymbolAddress((void**)&Kh,  g_Kh);
    float* Vh = nullptr;  cudaGetSymbolAddress((void**)&Vh,  g_Vh);
    float* at = nullptr;  cudaGetSymbolAddress((void**)&at,  g_attn);

    cudaFuncSetAttribute(flash_k, cudaFuncAttributeMaxDynamicSharedMemorySize, FLASH_SMEM);

    // 1) q_c = hidden @ q_a^T   [4096,1536]
    gemm128_k<<<dim3(QRANK/GN, MTOK/GM), 256>>>(hidden, qaw, qc, HID, HID, HID, QRANK);
    // 2) rmsnorm q_c (in place)
    rmsnorm_k<<<MTOK, 256>>>(qc, qaln, qc, QRANK, QRANK, QRANK);
    // 3) q = qcn @ q_b^T        [4096,6144]
    gemm128_k<<<dim3(QBOUT/GN, MTOK/GM), 256>>>(qc, qbw, q, QRANK, QRANK, QRANK, QBOUT);
    // 4) ckv = hidden @ kv_a^T  [4096,576]  (N not /128 -> 64x64 kernel)
    gemm64_k<<<dim3(KVAOUT/BN, MTOK/BM), 256>>>(hidden, kvaw, ckv, HID, HID, HID, KVAOUT);
    // 5) rmsnorm first 512 -> cn
    rmsnorm_k<<<MTOK, 256>>>(ckv, kvaln, cn, KVRANK, KVAOUT, KVRANK);
    // 6) kv = cn @ kv_b^T       [4096,8192]
    gemm128_k<<<dim3(KVBOUT/GN, MTOK/GM), 256>>>(cn, kvbw, kv, KVRANK, KVRANK, KVRANK, KVBOUT);
    // 7) build Q (rope) and K,V layouts
    build_q_k<<<dim3(SS, NH, BB), 128>>>(q, pos, Qh);
    build_kv_k<<<dim3(SS, BB), 256>>>(ckv, kv, pos, Kh, Vh);
    // 8) fused causal flash attention -> attn [tok, h*128]
    flash_k<<<dim3(SS/FM, BB*NH), 256, FLASH_SMEM>>>(Qh, Kh, Vh, at, rsqrtf((float)DQ));
    // 9) out = attn @ o^T       [4096,5120]
    gemm128_k<<<dim3(HID/GN, MTOK/GM), 256>>>(at, ow, out, NH*DV, NH*DV, NH*DV, HID);
}

// round 8
// speedup vs baseline: 1.6781x; 1.2853x over previous
#include <cuda_runtime.h>
#include <cuda_bf16.h>
#include <math.h>
#include <stdint.h>

// ---------------- problem constants ----------------
#define BB 2
#define SS 2048
#define HID 5120
#define NH 32
#define DNOPE 128
#define DROPE 64
#define DV 128
#define DQ 192
#define QRANK 1536
#define KVRANK 512
#define MTOK (BB*SS)            // 4096
#define KVAOUT (KVRANK+DROPE)   // 576
#define KVAPAD 640              // padded to /128 for 128x128 tiles
#define QBOUT (NH*DQ)           // 6144
#define KVBOUT (NH*(DNOPE+DV))  // 8192
#define ODIM  (NH*DV)           // 4096

typedef __nv_bfloat16 bf16;

// ---------------- scratch (static device, allocation-free) ----------------
__device__ float g_qc  [(size_t)MTOK*QRANK];
__device__ float g_q   [(size_t)MTOK*QBOUT];
__device__ float g_ckv [(size_t)MTOK*KVAPAD];
__device__ float g_kv  [(size_t)MTOK*KVBOUT];
__device__ float g_Qh  [(size_t)BB*NH*SS*DQ];
__device__ float g_Kh  [(size_t)BB*NH*SS*DQ];
__device__ float g_Vh  [(size_t)BB*NH*SS*DV];
// bf16 hi/lo operand buffers
__device__ bf16 g_hidh[(size_t)MTOK*HID],   g_hidl[(size_t)MTOK*HID];
__device__ bf16 g_qawh[(size_t)QRANK*HID],  g_qawl[(size_t)QRANK*HID];
__device__ bf16 g_qbwh[(size_t)QBOUT*QRANK],g_qbwl[(size_t)QBOUT*QRANK];
__device__ bf16 g_kvawh[(size_t)KVAPAD*HID],g_kvawl[(size_t)KVAPAD*HID];
__device__ bf16 g_kvbwh[(size_t)KVBOUT*KVRANK], g_kvbwl[(size_t)KVBOUT*KVRANK];
__device__ bf16 g_owh [(size_t)HID*ODIM],   g_owl [(size_t)HID*ODIM];
__device__ bf16 g_qch [(size_t)MTOK*QRANK], g_qcl [(size_t)MTOK*QRANK];
__device__ bf16 g_cnh [(size_t)MTOK*KVRANK],g_cnl [(size_t)MTOK*KVRANK];
__device__ bf16 g_ath [(size_t)MTOK*ODIM],  g_atl [(size_t)MTOK*ODIM];

// ---------------- warp-MMA helpers (plain sm_103-legal PTX) ----------------
__device__ __forceinline__ uint32_t s2u(const void* p) {
    uint32_t a;
    asm("{ .reg .u64 t; cvta.to.shared.u64 t, %1; cvt.u32.u64 %0, t; }" : "=r"(a) : "l"(p));
    return a;
}
#define SWZ128(off) ((off) ^ (((off) >> 3) & 0x70))

__device__ __forceinline__ void ldmx4(uint32_t r[4], uint32_t a) {
    asm volatile("ldmatrix.sync.aligned.m8n8.x4.shared.b16 {%0,%1,%2,%3}, [%4];"
        : "=r"(r[0]), "=r"(r[1]), "=r"(r[2]), "=r"(r[3]) : "r"(a));
}
__device__ __forceinline__ void ldmx2(uint32_t r[2], uint32_t a) {
    asm volatile("ldmatrix.sync.aligned.m8n8.x2.shared.b16 {%0,%1}, [%2];"
        : "=r"(r[0]), "=r"(r[1]) : "r"(a));
}
__device__ __forceinline__ void mma16816(float c[4], const uint32_t a[4], const uint32_t b[2]) {
    asm volatile(
        "mma.sync.aligned.m16n8k16.row.col.f32.bf16.bf16.f32 "
        "{%0,%1,%2,%3}, {%4,%5,%6,%7}, {%8,%9}, {%0,%1,%2,%3};"
        : "+f"(c[0]), "+f"(c[1]), "+f"(c[2]), "+f"(c[3])
        : "r"(a[0]), "r"(a[1]), "r"(a[2]), "r"(a[3]), "r"(b[0]), "r"(b[1]));
}

// ============ split-bf16 HMMA GEMM: C[m,n] = sum_k A[m,k]*B[n,k] ============
// A,B as (hi,lo) bf16 pairs, K-major rows. M%128==0, N%128==0, K%64==0.
#define TM 128
#define TN 128
#define TKC 64
#define TILE_B 16384           // 128 rows * 128 bytes (64 bf16)
#define SM_AH 0
#define SM_AL (SM_AH + TILE_B)
#define SM_BH (SM_AL + TILE_B)
#define SM_BL (SM_BH + TILE_B)
#define GEMM_SMEM (4 * TILE_B) // 65536

__global__ __launch_bounds__(256, 1)
void gemm_tc(const bf16* __restrict__ Ah, const bf16* __restrict__ Al,
             const bf16* __restrict__ Bh, const bf16* __restrict__ Bl,
             float* __restrict__ C, int K, int ldc)
{
    extern __shared__ char smem[];
    const uint32_t sb = s2u(smem);
    const int tid = threadIdx.x, wid = tid >> 5, lid = tid & 31;
    const int m0 = blockIdx.y * TM, n0 = blockIdx.x * TN;

    const int wm = wid & 1;      // 2 m-blocks of 64
    const int wn = wid >> 1;     // 4 n-blocks of 32

    // global-load mapping: thread t -> row t/2, 64B half (t&1)
    const int grow = tid >> 1;
    const int half = tid & 1;
    const uint4* rAh = reinterpret_cast<const uint4*>(Ah + (size_t)(m0 + grow) * K);
    const uint4* rAl = reinterpret_cast<const uint4*>(Al + (size_t)(m0 + grow) * K);
    const uint4* rBh = reinterpret_cast<const uint4*>(Bh + (size_t)(n0 + grow) * K);
    const uint4* rBl = reinterpret_cast<const uint4*>(Bl + (size_t)(n0 + grow) * K);

    // precompute swizzled store offsets (4 quads of 16B in this thread's half)
    uint32_t soff[4];
    #pragma unroll
    for (int j = 0; j < 4; j++)
        soff[j] = SWZ128((uint32_t)(grow * 128 + half * 64 + j * 16));

    float c[4][4][4];
    #pragma unroll
    for (int mt = 0; mt < 4; mt++)
        #pragma unroll
        for (int nt = 0; nt < 4; nt++)
            #pragma unroll
            for (int e = 0; e < 4; e++) c[mt][nt][e] = 0.f;

    // ldmatrix source addresses (per-lane, fixed across chunks except k-step quad)
    const int arow = wm * 64 + (lid & 15);   // + mt*16
    const int aq   = lid >> 4;               // 0/1 -> k half
    const int brow = wn * 32 + (lid & 7);    // + nt*8
    const int bq   = (lid >> 3) & 1;

    for (int k0 = 0; k0 < K; k0 += TKC) {
        const int base = k0 / 8 + half * 4;
        #pragma unroll
        for (int j = 0; j < 4; j++) {
            *reinterpret_cast<uint4*>(smem + SM_AH + soff[j]) = rAh[base + j];
            *reinterpret_cast<uint4*>(smem + SM_AL + soff[j]) = rAl[base + j];
            *reinterpret_cast<uint4*>(smem + SM_BH + soff[j]) = rBh[base + j];
            *reinterpret_cast<uint4*>(smem + SM_BL + soff[j]) = rBl[base + j];
        }
        __syncthreads();

        #pragma unroll
        for (int ks = 0; ks < 4; ks++) {
            uint32_t ah[4][4], al[4][4], bh[4][2], bl[4][2];
            #pragma unroll
            for (int mt = 0; mt < 4; mt++) {
                const uint32_t off = SWZ128((uint32_t)((arow + mt * 16) * 128 + (ks * 2 + aq) * 16));
                ldmx4(ah[mt], sb + SM_AH + off);
                ldmx4(al[mt], sb + SM_AL + off);
            }
            #pragma unroll
            for (int nt = 0; nt < 4; nt++) {
                const uint32_t off = SWZ128((uint32_t)((brow + nt * 8) * 128 + (ks * 2 + bq) * 16));
                ldmx2(bh[nt], sb + SM_BH + off);
                ldmx2(bl[nt], sb + SM_BL + off);
            }
            #pragma unroll
            for (int mt = 0; mt < 4; mt++)
                #pragma unroll
                for (int nt = 0; nt < 4; nt++) {
                    mma16816(c[mt][nt], ah[mt], bh[nt]);
                    mma16816(c[mt][nt], ah[mt], bl[nt]);
                    mma16816(c[mt][nt], al[mt], bh[nt]);
                }
        }
        __syncthreads();
    }

    // epilogue: fragment -> global fp32
    const int mbase = m0 + wm * 64 + (lid >> 2);
    const int nbase = n0 + wn * 32 + (lid & 3) * 2;
    #pragma unroll
    for (int mt = 0; mt < 4; mt++)
        #pragma unroll
        for (int nt = 0; nt < 4; nt++) {
            float* p0 = C + (size_t)(mbase + mt * 16) * ldc + nbase + nt * 8;
            float* p1 = p0 + 8 * ldc;
            *reinterpret_cast<float2*>(p0) = make_float2(c[mt][nt][0], c[mt][nt][1]);
            *reinterpret_cast<float2*>(p1) = make_float2(c[mt][nt][2], c[mt][nt][3]);
        }
}

// ---------------- fp32 -> (hi,lo) bf16 conversions ----------------
__global__ __launch_bounds__(256)
void cvt_pair_k(const float* __restrict__ x, bf16* __restrict__ h,
                bf16* __restrict__ l, size_t n)
{
    const size_t i = (size_t)blockIdx.x * 256 + threadIdx.x;
    if (i >= n) return;
    const float v = x[i];
    const bf16 hh = __float2bfloat16(v);
    h[i] = hh;
    l[i] = __float2bfloat16(v - __bfloat162float(hh));
}

__global__ __launch_bounds__(256)
void cvt_pad_k(const float* __restrict__ x, bf16* __restrict__ h,
               bf16* __restrict__ l, int rows, int cols, int padrows)
{
    const size_t i = (size_t)blockIdx.x * 256 + threadIdx.x;
    if (i >= (size_t)padrows * cols) return;
    const int r = (int)(i / cols);
    const float v = (r < rows) ? x[i] : 0.f;
    const bf16 hh = __float2bfloat16(v);
    h[i] = hh;
    l[i] = __float2bfloat16(v - __bfloat162float(hh));
}

// ---------------- RMSNorm -> (hi,lo) bf16 ----------------
__global__ __launch_bounds__(256)
void rmsnorm_pair_k(const float* __restrict__ x, const float* __restrict__ w,
                    bf16* __restrict__ yh, bf16* __restrict__ yl,
                    int n, int in_stride)
{
    const int row = blockIdx.x;
    const float* xr = x + (size_t)row * in_stride;
    bf16* yhr = yh + (size_t)row * n;
    bf16* ylr = yl + (size_t)row * n;
    __shared__ float red[256];
    float s = 0.f;
    for (int i = threadIdx.x; i < n; i += 256) { float v = xr[i]; s += v * v; }
    red[threadIdx.x] = s; __syncthreads();
    for (int o = 128; o; o >>= 1) {
        if (threadIdx.x < o) red[threadIdx.x] += red[threadIdx.x + o];
        __syncthreads();
    }
    const float r = rsqrtf(red[0] / n + 1e-6f);
    for (int i = threadIdx.x; i < n; i += 256) {
        const float v = xr[i] * r * w[i];
        const bf16 hh = __float2bfloat16(v);
        yhr[i] = hh;
        ylr[i] = __float2bfloat16(v - __bfloat162float(hh));
    }
}

// ---------------- build Q with RoPE: [tok, h*192] -> [b,h,s,192] ----------------
__global__ __launch_bounds__(128)
void build_q_k(const float* __restrict__ q, const int* __restrict__ pos,
               float* __restrict__ Qh)
{
    const int s = blockIdx.x, h = blockIdx.y, b = blockIdx.z;
    const float* in = q + ((size_t)(b * SS + s)) * QBOUT + h * DQ;
    float* out = Qh + (((size_t)(b * NH + h) * SS) + s) * DQ;
    const int t = threadIdx.x;
    out[t] = in[t];
    if (t < 32) {
        const float tp = (float)pos[b * SS + s];
        const float f = exp2f((float)t * (-13.2877123795494f / 32.f));
        float c, sn; sincosf(tp * f, &sn, &c);
        const float x0 = in[DNOPE + 2 * t];
        const float x1 = in[DNOPE + 2 * t + 1];
        out[DNOPE + t]      = x0 * c - x1 * sn;
        out[DNOPE + 32 + t] = x1 * c + x0 * sn;
    }
}

// ---------------- build K,V (ckv has padded stride KVAPAD) ----------------
__global__ __launch_bounds__(256)
void build_kv_k(const float* __restrict__ ckv, const float* __restrict__ kv,
                const int* __restrict__ pos,
                float* __restrict__ Kh, float* __restrict__ Vh)
{
    const int s = blockIdx.x, b = blockIdx.y;
    const size_t bs = (size_t)b * SS + s;
    __shared__ float kr[DROPE];
    const int tid = threadIdx.x;
    if (tid < 32) {
        const float tp = (float)pos[bs];
        const float f = exp2f((float)tid * (-13.2877123795494f / 32.f));
        float c, sn; sincosf(tp * f, &sn, &c);
        const float x0 = ckv[bs * KVAPAD + KVRANK + 2 * tid];
        const float x1 = ckv[bs * KVAPAD + KVRANK + 2 * tid + 1];
        kr[tid]      = x0 * c - x1 * sn;
        kr[32 + tid] = x1 * c + x0 * sn;
    }
    __syncthreads();
    const float* kvrow = kv + bs * KVBOUT;
    for (int idx = tid; idx < NH * DQ; idx += 256) {
        const int h = idx / DQ, d = idx % DQ;
        const float v = (d < DNOPE) ? kvrow[h * (DNOPE + DV) + d] : kr[d - DNOPE];
        Kh[(((size_t)(b * NH + h) * SS) + s) * DQ + d] = v;
    }
    for (int idx = tid; idx < NH * DV; idx += 256) {
        const int h = idx / DV, d = idx % DV;
        Vh[(((size_t)(b * NH + h) * SS) + s) * DV + d] = kvrow[h * (DNOPE + DV) + DNOPE + d];
    }
}

// ---------------- fused flash attention (causal, online softmax) ----------------
#define FM 64
#define FN 64
#define FLASH_SMEM ((DQ*FM + DQ*FN + FN*DV + FM*FN) * 4)   // 147456 bytes

__global__ __launch_bounds__(256)
void flash_k(const float* __restrict__ Qh, const float* __restrict__ Kh,
             const float* __restrict__ Vh, bf16* __restrict__ ath,
             bf16* __restrict__ atl, float scale)
{
    extern __shared__ float smf[];
    float* Qs = smf;                    // [DQ][FM]
    float* Ks = Qs + DQ * FM;           // [DQ][FN]
    float* Vs = Ks + DQ * FN;           // [FN][DV]
    float* Ps = Vs + FN * DV;           // [FM][FN]

    const int qt = blockIdx.x;
    const int bh = blockIdx.y;
    const int b  = bh / NH, h = bh % NH;
    const int q0 = qt * FM;
    const int tid = threadIdx.x;
    const int tx = tid & 15, ty = tid >> 4;

    const float* Qg = Qh + ((size_t)bh * SS + q0) * DQ;
    const float* Kg = Kh + (size_t)bh * SS * DQ;
    const float* Vg = Vh + (size_t)bh * SS * DV;

    for (int idx = tid; idx < FM * (DQ / 4); idx += 256) {
        const int row = idx / (DQ / 4);
        const int d4  = (idx % (DQ / 4)) * 4;
        float4 v = *reinterpret_cast<const float4*>(&Qg[(size_t)row * DQ + d4]);
        Qs[(d4 + 0) * FM + row] = v.x * scale;
        Qs[(d4 + 1) * FM + row] = v.y * scale;
        Qs[(d4 + 2) * FM + row] = v.z * scale;
        Qs[(d4 + 3) * FM + row] = v.w * scale;
    }

    float o[4][8];
    #pragma unroll
    for (int i = 0; i < 4; i++)
        #pragma unroll
        for (int j = 0; j < 8; j++) o[i][j] = 0.f;
    float mrow[4] = {-1e30f, -1e30f, -1e30f, -1e30f};
    float lrow[4] = {0.f, 0.f, 0.f, 0.f};

    for (int kt = 0; kt <= qt; kt++) {
        const int k0 = kt * FN;
        __syncthreads();

        for (int idx = tid; idx < FN * (DQ / 4); idx += 256) {
            const int row = idx / (DQ / 4);
            const int d4  = (idx % (DQ / 4)) * 4;
            float4 v = *reinterpret_cast<const float4*>(&Kg[(size_t)(k0 + row) * DQ + d4]);
            Ks[(d4 + 0) * FN + row] = v.x;
            Ks[(d4 + 1) * FN + row] = v.y;
            Ks[(d4 + 2) * FN + row] = v.z;
            Ks[(d4 + 3) * FN + row] = v.w;
        }
        for (int idx = tid; idx < FN * DV / 4; idx += 256) {
            *reinterpret_cast<float4*>(&Vs[idx * 4]) =
                *reinterpret_cast<const float4*>(&Vg[(size_t)k0 * DV + idx * 4]);
        }
        __syncthreads();

        float s[4][4] = {};
        #pragma unroll 4
        for (int kk = 0; kk < DQ; kk++) {
            float4 qv = *reinterpret_cast<const float4*>(&Qs[kk * FM + ty * 4]);
            float4 kv = *reinterpret_cast<const float4*>(&Ks[kk * FN + tx * 4]);
            float qa[4] = {qv.x, qv.y, qv.z, qv.w};
            float ka[4] = {kv.x, kv.y, kv.z, kv.w};
            #pragma unroll
            for (int i = 0; i < 4; i++)
                #pragma unroll
                for (int j = 0; j < 4; j++)
                    s[i][j] += qa[i] * ka[j];
        }

        if (kt == qt) {
            #pragma unroll
            for (int i = 0; i < 4; i++)
                #pragma unroll
                for (int j = 0; j < 4; j++)
                    if (tx * 4 + j > ty * 4 + i) s[i][j] = -1e30f;
        }

        float alpha[4];
        #pragma unroll
        for (int i = 0; i < 4; i++) {
            float tm = fmaxf(fmaxf(s[i][0], s[i][1]), fmaxf(s[i][2], s[i][3]));
            #pragma unroll
            for (int w = 1; w < 16; w <<= 1)
                tm = fmaxf(tm, __shfl_xor_sync(0xffffffffu, tm, w));
            const float mn = fmaxf(mrow[i], tm);
            alpha[i] = __expf(mrow[i] - mn);
            float rs = 0.f;
            #pragma unroll
            for (int j = 0; j < 4; j++) { s[i][j] = __expf(s[i][j] - mn); rs += s[i][j]; }
            #pragma unroll
            for (int w = 1; w < 16; w <<= 1)
                rs += __shfl_xor_sync(0xffffffffu, rs, w);
            lrow[i] = lrow[i] * alpha[i] + rs;
            mrow[i] = mn;
            *reinterpret_cast<float4*>(&Ps[(ty * 4 + i) * FN + tx * 4]) =
                make_float4(s[i][0], s[i][1], s[i][2], s[i][3]);
        }
        __syncthreads();

        #pragma unroll
        for (int i = 0; i < 4; i++)
            #pragma unroll
            for (int j = 0; j < 8; j++) o[i][j] *= alpha[i];
        #pragma unroll 2
        for (int kk = 0; kk < FN; kk++) {
            float4 va = *reinterpret_cast<const float4*>(&Vs[kk * DV + tx * 4]);
            float4 vb = *reinterpret_cast<const float4*>(&Vs[kk * DV + 64 + tx * 4]);
            #pragma unroll
            for (int i = 0; i < 4; i++) {
                const float p = Ps[(ty * 4 + i) * FN + kk];
                o[i][0] += p * va.x; o[i][1] += p * va.y;
                o[i][2] += p * va.z; o[i][3] += p * va.w;
                o[i][4] += p * vb.x; o[i][5] += p * vb.y;
                o[i][6] += p * vb.z; o[i][7] += p * vb.w;
            }
        }
    }

    // epilogue: normalize + emit (hi,lo) bf16 pairs for the o_proj GEMM
    #pragma unroll
    for (int i = 0; i < 4; i++) {
        const float inv = 1.f / lrow[i];
        const int r = q0 + ty * 4 + i;
        const size_t base = ((size_t)(b * SS + r)) * ODIM + h * DV;
        #pragma unroll
        for (int half = 0; half < 2; half++) {
            const int cbase = half * 64 + tx * 4;
            #pragma unroll
            for (int j = 0; j < 4; j++) {
                const float v = o[i][half * 4 + j] * inv;
                const bf16 hh = __float2bfloat16(v);
                ath[base + cbase + j] = hh;
                atl[base + cbase + j] = __float2bfloat16(v - __bfloat162float(hh));
            }
        }
    }
}

// ---------------- launch ----------------
extern "C" void kernel_launch(void* const* d_in, const int* in_sizes, int n_in,
                              void* d_out, int out_size)
{
    const float* hidden = (const float*)d_in[0];
    const float* qaw    = (const float*)d_in[1];
    const float* qaln   = (const float*)d_in[2];
    const float* qbw    = (const float*)d_in[3];
    const float* kvaw   = (const float*)d_in[4];
    const float* kvaln  = (const float*)d_in[5];
    const float* kvbw   = (const float*)d_in[6];
    const float* ow     = (const float*)d_in[7];
    const int*   pos    = (const int*)d_in[8];
    // d_in[9] = attention_mask (causal tril) — enforced analytically in flash kernel
    float* out = (float*)d_out;

    float *qc, *q, *ckv, *kv, *Qh, *Kh, *Vh;
    bf16 *hidh, *hidl, *qawh, *qawl, *qbwh, *qbwl, *kvawh, *kvawl, *kvbwh, *kvbwl;
    bf16 *owh, *owl, *qch, *qcl, *cnh, *cnl, *ath, *atl;
    cudaGetSymbolAddress((void**)&qc,  g_qc);   cudaGetSymbolAddress((void**)&q,    g_q);
    cudaGetSymbolAddress((void**)&ckv, g_ckv);  cudaGetSymbolAddress((void**)&kv,   g_kv);
    cudaGetSymbolAddress((void**)&Qh,  g_Qh);   cudaGetSymbolAddress((void**)&Kh,   g_Kh);
    cudaGetSymbolAddress((void**)&Vh,  g_Vh);
    cudaGetSymbolAddress((void**)&hidh, g_hidh); cudaGetSymbolAddress((void**)&hidl, g_hidl);
    cudaGetSymbolAddress((void**)&qawh, g_qawh); cudaGetSymbolAddress((void**)&qawl, g_qawl);
    cudaGetSymbolAddress((void**)&qbwh, g_qbwh); cudaGetSymbolAddress((void**)&qbwl, g_qbwl);
    cudaGetSymbolAddress((void**)&kvawh, g_kvawh); cudaGetSymbolAddress((void**)&kvawl, g_kvawl);
    cudaGetSymbolAddress((void**)&kvbwh, g_kvbwh); cudaGetSymbolAddress((void**)&kvbwl, g_kvbwl);
    cudaGetSymbolAddress((void**)&owh, g_owh);   cudaGetSymbolAddress((void**)&owl, g_owl);
    cudaGetSymbolAddress((void**)&qch, g_qch);   cudaGetSymbolAddress((void**)&qcl, g_qcl);
    cudaGetSymbolAddress((void**)&cnh, g_cnh);   cudaGetSymbolAddress((void**)&cnl, g_cnl);
    cudaGetSymbolAddress((void**)&ath, g_ath);   cudaGetSymbolAddress((void**)&atl, g_atl);

    cudaFuncSetAttribute(flash_k, cudaFuncAttributeMaxDynamicSharedMemorySize, FLASH_SMEM);
    cudaFuncSetAttribute(gemm_tc, cudaFuncAttributeMaxDynamicSharedMemorySize, GEMM_SMEM);

    #define CVT(x, h, l, n) cvt_pair_k<<<(unsigned)(((size_t)(n) + 255) / 256), 256>>>(x, h, l, (size_t)(n))
    // 0) one-time fp32 -> (hi,lo) bf16 operand conversions
    CVT(hidden, hidh, hidl, (size_t)MTOK * HID);
    CVT(qaw,    qawh, qawl, (size_t)QRANK * HID);
    CVT(qbw,    qbwh, qbwl, (size_t)QBOUT * QRANK);
    CVT(kvbw,   kvbwh, kvbwl, (size_t)KVBOUT * KVRANK);
    CVT(ow,     owh,  owl,  (size_t)HID * ODIM);
    cvt_pad_k<<<(unsigned)(((size_t)KVAPAD * HID + 255) / 256), 256>>>(
        kvaw, kvawh, kvawl, KVAOUT, HID, KVAPAD);

    // 1) q_c = hidden @ q_a^T   [4096,1536]
    gemm_tc<<<dim3(QRANK/TN, MTOK/TM), 256, GEMM_SMEM>>>(hidh, hidl, qawh, qawl, qc, HID, QRANK);
    // 2) rmsnorm(q_c) -> bf16 pair
    rmsnorm_pair_k<<<MTOK, 256>>>(qc, qaln, qch, qcl, QRANK, QRANK);
    // 3) q = qcn @ q_b^T        [4096,6144]
    gemm_tc<<<dim3(QBOUT/TN, MTOK/TM), 256, GEMM_SMEM>>>(qch, qcl, qbwh, qbwl, q, QRANK, QBOUT);
    // 4) ckv = hidden @ kv_a^T  [4096,640 padded]
    gemm_tc<<<dim3(KVAPAD/TN, MTOK/TM), 256, GEMM_SMEM>>>(hidh, hidl, kvawh, kvawl, ckv, HID, KVAPAD);
    // 5) rmsnorm(ckv[:, :512]) -> bf16 pair
    rmsnorm_pair_k<<<MTOK, 256>>>(ckv, kvaln, cnh, cnl, KVRANK, KVAPAD);
    // 6) kv = cn @ kv_b^T       [4096,8192]
    gemm_tc<<<dim3(KVBOUT/TN, MTOK/TM), 256, GEMM_SMEM>>>(cnh, cnl, kvbwh, kvbwl, kv, KVRANK, KVBOUT);
    // 7) build Q (rope) and K,V layouts
    build_q_k<<<dim3(SS, NH, BB), 128>>>(q, pos, Qh);
    build_kv_k<<<dim3(SS, BB), 256>>>(ckv, kv, pos, Kh, Vh);
    // 8) fused causal flash attention -> attn (hi,lo) bf16 [tok, h*128]
    flash_k<<<dim3(SS/FM, BB*NH), 256, FLASH_SMEM>>>(Qh, Kh, Vh, ath, atl, rsqrtf((float)DQ));
    // 9) out = attn @ o^T       [4096,5120]
    gemm_tc<<<dim3(HID/TN, MTOK/TM), 256, GEMM_SMEM>>>(ath, atl, owh, owl, out, ODIM, HID);
}

// round 9
// speedup vs baseline: 2.4575x; 1.4644x over previous
#include <cuda_runtime.h>
#include <cuda_bf16.h>
#include <math.h>
#include <stdint.h>

// ---------------- problem constants ----------------
#define BB 2
#define SS 2048
#define HID 5120
#define NH 32
#define DNOPE 128
#define DROPE 64
#define DV 128
#define DQ 192
#define QRANK 1536
#define KVRANK 512
#define MTOK (BB*SS)            // 4096
#define KVAOUT (KVRANK+DROPE)   // 576
#define KVAPAD 640              // padded to /128 for 128x128 tiles
#define QBOUT (NH*DQ)           // 6144
#define KVBOUT (NH*(DNOPE+DV))  // 8192
#define ODIM  (NH*DV)           // 4096

typedef __nv_bfloat16 bf16;

// ---------------- scratch (static device, allocation-free) ----------------
__device__ float g_qc  [(size_t)MTOK*QRANK];
__device__ float g_q   [(size_t)MTOK*QBOUT];
__device__ float g_ckv [(size_t)MTOK*KVAPAD];
__device__ float g_kv  [(size_t)MTOK*KVBOUT];
// bf16 hi/lo operand buffers (projections)
__device__ bf16 g_hidh[(size_t)MTOK*HID],   g_hidl[(size_t)MTOK*HID];
__device__ bf16 g_qawh[(size_t)QRANK*HID],  g_qawl[(size_t)QRANK*HID];
__device__ bf16 g_qbwh[(size_t)QBOUT*QRANK],g_qbwl[(size_t)QBOUT*QRANK];
__device__ bf16 g_kvawh[(size_t)KVAPAD*HID],g_kvawl[(size_t)KVAPAD*HID];
__device__ bf16 g_kvbwh[(size_t)KVBOUT*KVRANK], g_kvbwl[(size_t)KVBOUT*KVRANK];
__device__ bf16 g_owh [(size_t)HID*ODIM],   g_owl [(size_t)HID*ODIM];
__device__ bf16 g_qch [(size_t)MTOK*QRANK], g_qcl [(size_t)MTOK*QRANK];
__device__ bf16 g_cnh [(size_t)MTOK*KVRANK],g_cnl [(size_t)MTOK*KVRANK];
__device__ bf16 g_ath [(size_t)MTOK*ODIM],  g_atl [(size_t)MTOK*ODIM];
// bf16 hi/lo attention operands [b,h][s][*]
__device__ bf16 g_Qhh[(size_t)BB*NH*SS*DQ], g_Qhl[(size_t)BB*NH*SS*DQ];
__device__ bf16 g_Khh[(size_t)BB*NH*SS*DQ], g_Khl[(size_t)BB*NH*SS*DQ];
__device__ bf16 g_Vhh[(size_t)BB*NH*SS*DV], g_Vhl[(size_t)BB*NH*SS*DV];

// ---------------- warp-MMA helpers (plain sm_103-legal PTX) ----------------
__device__ __forceinline__ uint32_t s2u(const void* p) {
    uint32_t a;
    asm("{ .reg .u64 t; cvta.to.shared.u64 t, %1; cvt.u32.u64 %0, t; }" : "=r"(a) : "l"(p));
    return a;
}
#define SWZ128(off) ((off) ^ (((off) >> 3) & 0x70))   // 128B-row panels
#define SWZV(off)   ((off) ^ (((off) >> 4) & 0x70))   // 256B-row V panel

__device__ __forceinline__ void ldmx4(uint32_t r[4], uint32_t a) {
    asm volatile("ldmatrix.sync.aligned.m8n8.x4.shared.b16 {%0,%1,%2,%3}, [%4];"
        : "=r"(r[0]), "=r"(r[1]), "=r"(r[2]), "=r"(r[3]) : "r"(a));
}
__device__ __forceinline__ void ldmx2(uint32_t r[2], uint32_t a) {
    asm volatile("ldmatrix.sync.aligned.m8n8.x2.shared.b16 {%0,%1}, [%2];"
        : "=r"(r[0]), "=r"(r[1]) : "r"(a));
}
__device__ __forceinline__ void ldmx2t(uint32_t r[2], uint32_t a) {
    asm volatile("ldmatrix.sync.aligned.m8n8.x2.trans.shared.b16 {%0,%1}, [%2];"
        : "=r"(r[0]), "=r"(r[1]) : "r"(a));
}
__device__ __forceinline__ void mma16816(float c[4], const uint32_t a[4], const uint32_t b[2]) {
    asm volatile(
        "mma.sync.aligned.m16n8k16.row.col.f32.bf16.bf16.f32 "
        "{%0,%1,%2,%3}, {%4,%5,%6,%7}, {%8,%9}, {%0,%1,%2,%3};"
        : "+f"(c[0]), "+f"(c[1]), "+f"(c[2]), "+f"(c[3])
        : "r"(a[0]), "r"(a[1]), "r"(a[2]), "r"(a[3]), "r"(b[0]), "r"(b[1]));
}
__device__ __forceinline__ uint32_t packbf2(float lo, float hi) {
    __nv_bfloat162 t = __floats2bfloat162_rn(lo, hi);
    return *reinterpret_cast<uint32_t*>(&t);
}

// ============ split-bf16 HMMA GEMM: C[m,n] = sum_k A[m,k]*B[n,k] ============
#define TM 128
#define TN 128
#define TKC 64
#define TILE_B 16384
#define SM_AH 0
#define SM_AL (SM_AH + TILE_B)
#define SM_BH (SM_AL + TILE_B)
#define SM_BL (SM_BH + TILE_B)
#define GEMM_SMEM (4 * TILE_B)

__global__ __launch_bounds__(256, 1)
void gemm_tc(const bf16* __restrict__ Ah, const bf16* __restrict__ Al,
             const bf16* __restrict__ Bh, const bf16* __restrict__ Bl,
             float* __restrict__ C, int K, int ldc)
{
    extern __shared__ char smem[];
    const uint32_t sb = s2u(smem);
    const int tid = threadIdx.x, wid = tid >> 5, lid = tid & 31;
    const int m0 = blockIdx.y * TM, n0 = blockIdx.x * TN;
    const int wm = wid & 1, wn = wid >> 1;

    const int grow = tid >> 1;
    const int half = tid & 1;
    const uint4* rAh = reinterpret_cast<const uint4*>(Ah + (size_t)(m0 + grow) * K);
    const uint4* rAl = reinterpret_cast<const uint4*>(Al + (size_t)(m0 + grow) * K);
    const uint4* rBh = reinterpret_cast<const uint4*>(Bh + (size_t)(n0 + grow) * K);
    const uint4* rBl = reinterpret_cast<const uint4*>(Bl + (size_t)(n0 + grow) * K);

    uint32_t soff[4];
    #pragma unroll
    for (int j = 0; j < 4; j++)
        soff[j] = SWZ128((uint32_t)(grow * 128 + half * 64 + j * 16));

    float c[4][4][4];
    #pragma unroll
    for (int mt = 0; mt < 4; mt++)
        #pragma unroll
        for (int nt = 0; nt < 4; nt++)
            #pragma unroll
            for (int e = 0; e < 4; e++) c[mt][nt][e] = 0.f;

    const int arow = wm * 64 + (lid & 15);
    const int aq   = lid >> 4;
    const int brow = wn * 32 + (lid & 7);
    const int bq   = (lid >> 3) & 1;

    for (int k0 = 0; k0 < K; k0 += TKC) {
        const int base = k0 / 8 + half * 4;
        #pragma unroll
        for (int j = 0; j < 4; j++) {
            *reinterpret_cast<uint4*>(smem + SM_AH + soff[j]) = rAh[base + j];
            *reinterpret_cast<uint4*>(smem + SM_AL + soff[j]) = rAl[base + j];
            *reinterpret_cast<uint4*>(smem + SM_BH + soff[j]) = rBh[base + j];
            *reinterpret_cast<uint4*>(smem + SM_BL + soff[j]) = rBl[base + j];
        }
        __syncthreads();

        #pragma unroll
        for (int ks = 0; ks < 4; ks++) {
            uint32_t ah[4][4], al[4][4], bh[4][2], bl[4][2];
            #pragma unroll
            for (int mt = 0; mt < 4; mt++) {
                const uint32_t off = SWZ128((uint32_t)((arow + mt * 16) * 128 + (ks * 2 + aq) * 16));
                ldmx4(ah[mt], sb + SM_AH + off);
                ldmx4(al[mt], sb + SM_AL + off);
            }
            #pragma unroll
            for (int nt = 0; nt < 4; nt++) {
                const uint32_t off = SWZ128((uint32_t)((brow + nt * 8) * 128 + (ks * 2 + bq) * 16));
                ldmx2(bh[nt], sb + SM_BH + off);
                ldmx2(bl[nt], sb + SM_BL + off);
            }
            #pragma unroll
            for (int mt = 0; mt < 4; mt++)
                #pragma unroll
                for (int nt = 0; nt < 4; nt++) {
                    mma16816(c[mt][nt], ah[mt], bh[nt]);
                    mma16816(c[mt][nt], ah[mt], bl[nt]);
                    mma16816(c[mt][nt], al[mt], bh[nt]);
                }
        }
        __syncthreads();
    }

    const int mbase = m0 + wm * 64 + (lid >> 2);
    const int nbase = n0 + wn * 32 + (lid & 3) * 2;
    #pragma unroll
    for (int mt = 0; mt < 4; mt++)
        #pragma unroll
        for (int nt = 0; nt < 4; nt++) {
            float* p0 = C + (size_t)(mbase + mt * 16) * ldc + nbase + nt * 8;
            float* p1 = p0 + 8 * ldc;
            *reinterpret_cast<float2*>(p0) = make_float2(c[mt][nt][0], c[mt][nt][1]);
            *reinterpret_cast<float2*>(p1) = make_float2(c[mt][nt][2], c[mt][nt][3]);
        }
}

// ---------------- fp32 -> (hi,lo) bf16 conversions ----------------
__global__ __launch_bounds__(256)
void cvt_pair_k(const float* __restrict__ x, bf16* __restrict__ h,
                bf16* __restrict__ l, size_t n)
{
    const size_t i = (size_t)blockIdx.x * 256 + threadIdx.x;
    if (i >= n) return;
    const float v = x[i];
    const bf16 hh = __float2bfloat16(v);
    h[i] = hh;
    l[i] = __float2bfloat16(v - __bfloat162float(hh));
}

__global__ __launch_bounds__(256)
void cvt_pad_k(const float* __restrict__ x, bf16* __restrict__ h,
               bf16* __restrict__ l, int rows, int cols, int padrows)
{
    const size_t i = (size_t)blockIdx.x * 256 + threadIdx.x;
    if (i >= (size_t)padrows * cols) return;
    const int r = (int)(i / cols);
    const float v = (r < rows) ? x[i] : 0.f;
    const bf16 hh = __float2bfloat16(v);
    h[i] = hh;
    l[i] = __float2bfloat16(v - __bfloat162float(hh));
}

// ---------------- RMSNorm -> (hi,lo) bf16 ----------------
__global__ __launch_bounds__(256)
void rmsnorm_pair_k(const float* __restrict__ x, const float* __restrict__ w,
                    bf16* __restrict__ yh, bf16* __restrict__ yl,
                    int n, int in_stride)
{
    const int row = blockIdx.x;
    const float* xr = x + (size_t)row * in_stride;
    bf16* yhr = yh + (size_t)row * n;
    bf16* ylr = yl + (size_t)row * n;
    __shared__ float red[256];
    float s = 0.f;
    for (int i = threadIdx.x; i < n; i += 256) { float v = xr[i]; s += v * v; }
    red[threadIdx.x] = s; __syncthreads();
    for (int o = 128; o; o >>= 1) {
        if (threadIdx.x < o) red[threadIdx.x] += red[threadIdx.x + o];
        __syncthreads();
    }
    const float r = rsqrtf(red[0] / n + 1e-6f);
    for (int i = threadIdx.x; i < n; i += 256) {
        const float v = xr[i] * r * w[i];
        const bf16 hh = __float2bfloat16(v);
        yhr[i] = hh;
        ylr[i] = __float2bfloat16(v - __bfloat162float(hh));
    }
}

// ------- build Q (RoPE + scale) -> bf16 hi/lo [b,h,s,192] -------
__global__ __launch_bounds__(128)
void build_q_k(const float* __restrict__ q, const int* __restrict__ pos,
               bf16* __restrict__ Qhh, bf16* __restrict__ Qhl, float scale)
{
    const int s = blockIdx.x, h = blockIdx.y, b = blockIdx.z;
    const float* in = q + ((size_t)(b * SS + s)) * QBOUT + h * DQ;
    const size_t ob = (((size_t)(b * NH + h) * SS) + s) * DQ;
    const int t = threadIdx.x;
    {
        const float v = in[t] * scale;
        const bf16 hh = __float2bfloat16(v);
        Qhh[ob + t] = hh;
        Qhl[ob + t] = __float2bfloat16(v - __bfloat162float(hh));
    }
    if (t < 32) {
        const float tp = (float)pos[b * SS + s];
        const float f = exp2f((float)t * (-13.2877123795494f / 32.f));
        float c, sn; sincosf(tp * f, &sn, &c);
        const float x0 = in[DNOPE + 2 * t];
        const float x1 = in[DNOPE + 2 * t + 1];
        const float v0 = (x0 * c - x1 * sn) * scale;
        const float v1 = (x1 * c + x0 * sn) * scale;
        bf16 h0 = __float2bfloat16(v0), h1 = __float2bfloat16(v1);
        Qhh[ob + DNOPE + t]      = h0;
        Qhl[ob + DNOPE + t]      = __float2bfloat16(v0 - __bfloat162float(h0));
        Qhh[ob + DNOPE + 32 + t] = h1;
        Qhl[ob + DNOPE + 32 + t] = __float2bfloat16(v1 - __bfloat162float(h1));
    }
}

// ------- build K,V -> bf16 hi/lo [b,h,s,*] -------
__global__ __launch_bounds__(256)
void build_kv_k(const float* __restrict__ ckv, const float* __restrict__ kv,
                const int* __restrict__ pos,
                bf16* __restrict__ Khh, bf16* __restrict__ Khl,
                bf16* __restrict__ Vhh, bf16* __restrict__ Vhl)
{
    const int s = blockIdx.x, b = blockIdx.y;
    const size_t bs = (size_t)b * SS + s;
    __shared__ float kr[DROPE];
    const int tid = threadIdx.x;
    if (tid < 32) {
        const float tp = (float)pos[bs];
        const float f = exp2f((float)tid * (-13.2877123795494f / 32.f));
        float c, sn; sincosf(tp * f, &sn, &c);
        const float x0 = ckv[bs * KVAPAD + KVRANK + 2 * tid];
        const float x1 = ckv[bs * KVAPAD + KVRANK + 2 * tid + 1];
        kr[tid]      = x0 * c - x1 * sn;
        kr[32 + tid] = x1 * c + x0 * sn;
    }
    __syncthreads();
    const float* kvrow = kv + bs * KVBOUT;
    for (int idx = tid; idx < NH * DQ; idx += 256) {
        const int h = idx / DQ, d = idx % DQ;
        const float v = (d < DNOPE) ? kvrow[h * (DNOPE + DV) + d] : kr[d - DNOPE];
        const size_t o = (((size_t)(b * NH + h) * SS) + s) * DQ + d;
        const bf16 hh = __float2bfloat16(v);
        Khh[o] = hh;
        Khl[o] = __float2bfloat16(v - __bfloat162float(hh));
    }
    for (int idx = tid; idx < NH * DV; idx += 256) {
        const int h = idx / DV, d = idx % DV;
        const float v = kvrow[h * (DNOPE + DV) + DNOPE + d];
        const size_t o = (((size_t)(b * NH + h) * SS) + s) * DV + d;
        const bf16 hh = __float2bfloat16(v);
        Vhh[o] = hh;
        Vhl[o] = __float2bfloat16(v - __bfloat162float(hh));
    }
}

// ====== HMMA flash attention: 128 q-rows/CTA, 64-key tiles, split bf16 ======
#define FQM 128
#define FKN 64
// smem byte offsets
#define FQH0 0                         // 3 panels x 16384
#define FQL0 49152
#define FKH0 98304                     // 3 panels x 8192
#define FKL0 122880
#define FVH0 147456                    // 16384 (64 x 256B swizzled)
#define FVL0 163840
#define FL_SMEM 180224

__global__ __launch_bounds__(256, 1)
void flashmma_k(const bf16* __restrict__ Qhh, const bf16* __restrict__ Qhl,
                const bf16* __restrict__ Khh, const bf16* __restrict__ Khl,
                const bf16* __restrict__ Vhh, const bf16* __restrict__ Vhl,
                bf16* __restrict__ ath, bf16* __restrict__ atl)
{
    extern __shared__ char sm[];
    const uint32_t sb = s2u(sm);
    const int tid = threadIdx.x, w = tid >> 5, l = tid & 31;
    const int qt = blockIdx.x, bh = blockIdx.y;
    const int b = bh / NH, h = bh % NH;
    const int q0 = qt * FQM;

    // ---- load Q tile (once) ----
    const uint4* Qh4 = reinterpret_cast<const uint4*>(Qhh + ((size_t)bh * SS + q0) * DQ);
    const uint4* Ql4 = reinterpret_cast<const uint4*>(Qhl + ((size_t)bh * SS + q0) * DQ);
    for (int idx = tid; idx < 128 * 24; idx += 256) {
        const int row = idx / 24, u = idx % 24;
        const int p = u >> 3, qd = u & 7;
        const uint32_t off = (uint32_t)(p * 16384) + SWZ128((uint32_t)(row * 128 + qd * 16));
        *reinterpret_cast<uint4*>(sm + FQH0 + off) = Qh4[row * 24 + u];
        *reinterpret_cast<uint4*>(sm + FQL0 + off) = Ql4[row * 24 + u];
    }

    float oacc[16][4];
    #pragma unroll
    for (int i = 0; i < 16; i++)
        #pragma unroll
        for (int e = 0; e < 4; e++) oacc[i][e] = 0.f;
    float mrow[2] = {-1e30f, -1e30f};
    float lsum[2] = {0.f, 0.f};

    const int r0 = q0 + w * 16 + (l >> 2);
    const int r1 = r0 + 8;

    const int ktmax = 2 * qt + 1;
    for (int kt = 0; kt <= ktmax; kt++) {
        const int k0 = kt * FKN;
        __syncthreads();
        // ---- load K, V tiles ----
        const uint4* Kh4 = reinterpret_cast<const uint4*>(Khh + ((size_t)bh * SS + k0) * DQ);
        const uint4* Kl4 = reinterpret_cast<const uint4*>(Khl + ((size_t)bh * SS + k0) * DQ);
        const uint4* Vh4 = reinterpret_cast<const uint4*>(Vhh + ((size_t)bh * SS + k0) * DV);
        const uint4* Vl4 = reinterpret_cast<const uint4*>(Vhl + ((size_t)bh * SS + k0) * DV);
        for (int idx = tid; idx < 64 * 24; idx += 256) {
            const int row = idx / 24, u = idx % 24;
            const int p = u >> 3, qd = u & 7;
            const uint32_t off = (uint32_t)(p * 8192) + SWZ128((uint32_t)(row * 128 + qd * 16));
            *reinterpret_cast<uint4*>(sm + FKH0 + off) = Kh4[row * 24 + u];
            *reinterpret_cast<uint4*>(sm + FKL0 + off) = Kl4[row * 24 + u];
        }
        for (int idx = tid; idx < 64 * 16; idx += 256) {
            const int row = idx >> 4, qd = idx & 15;
            const uint32_t off = SWZV((uint32_t)(row * 256 + qd * 16));
            *reinterpret_cast<uint4*>(sm + FVH0 + off) = Vh4[row * 16 + qd];
            *reinterpret_cast<uint4*>(sm + FVL0 + off) = Vl4[row * 16 + qd];
        }
        __syncthreads();

        // ---- S = Q @ K^T (split-bf16, fp32 accum) ----
        float sacc[8][4];
        #pragma unroll
        for (int nt = 0; nt < 8; nt++)
            #pragma unroll
            for (int e = 0; e < 4; e++) sacc[nt][e] = 0.f;

        #pragma unroll
        for (int p = 0; p < 3; p++)
            #pragma unroll
            for (int ks = 0; ks < 4; ks++) {
                uint32_t ah[4], al[4];
                const uint32_t aoff = (uint32_t)(p * 16384) +
                    SWZ128((uint32_t)((w * 16 + (l & 15)) * 128 + (ks * 2 + (l >> 4)) * 16));
                ldmx4(ah, sb + FQH0 + aoff);
                ldmx4(al, sb + FQL0 + aoff);
                #pragma unroll
                for (int nt = 0; nt < 8; nt++) {
                    uint32_t bh_[2], bl_[2];
                    const uint32_t boff = (uint32_t)(p * 8192) +
                        SWZ128((uint32_t)((nt * 8 + (l & 7)) * 128 + (ks * 2 + ((l >> 3) & 1)) * 16));
                    ldmx2(bh_, sb + FKH0 + boff);
                    ldmx2(bl_, sb + FKL0 + boff);
                    mma16816(sacc[nt], ah, bh_);
                    mma16816(sacc[nt], ah, bl_);
                    mma16816(sacc[nt], al, bh_);
                }
            }

        // ---- causal mask (only the two diagonal-adjacent blocks) ----
        if (kt >= 2 * qt) {
            #pragma unroll
            for (int nt = 0; nt < 8; nt++) {
                const int c0 = k0 + nt * 8 + (l & 3) * 2;
                if (c0     > r0) sacc[nt][0] = -1e30f;
                if (c0 + 1 > r0) sacc[nt][1] = -1e30f;
                if (c0     > r1) sacc[nt][2] = -1e30f;
                if (c0 + 1 > r1) sacc[nt][3] = -1e30f;
            }
        }

        // ---- online softmax (per fragment row) ----
        float alpha[2];
        #pragma unroll
        for (int sub = 0; sub < 2; sub++) {
            float tm = -1e30f;
            #pragma unroll
            for (int nt = 0; nt < 8; nt++)
                tm = fmaxf(tm, fmaxf(sacc[nt][2 * sub], sacc[nt][2 * sub + 1]));
            tm = fmaxf(tm, __shfl_xor_sync(0xffffffffu, tm, 1));
            tm = fmaxf(tm, __shfl_xor_sync(0xffffffffu, tm, 2));
            const float mn = fmaxf(mrow[sub], tm);
            alpha[sub] = __expf(mrow[sub] - mn);
            float rs = 0.f;
            #pragma unroll
            for (int nt = 0; nt < 8; nt++) {
                sacc[nt][2 * sub]     = __expf(sacc[nt][2 * sub] - mn);
                sacc[nt][2 * sub + 1] = __expf(sacc[nt][2 * sub + 1] - mn);
                rs += sacc[nt][2 * sub] + sacc[nt][2 * sub + 1];
            }
            rs += __shfl_xor_sync(0xffffffffu, rs, 1);
            rs += __shfl_xor_sync(0xffffffffu, rs, 2);
            lsum[sub] = lsum[sub] * alpha[sub] + rs;
            mrow[sub] = mn;
        }
        #pragma unroll
        for (int ntv = 0; ntv < 16; ntv++) {
            oacc[ntv][0] *= alpha[0]; oacc[ntv][1] *= alpha[0];
            oacc[ntv][2] *= alpha[1]; oacc[ntv][3] *= alpha[1];
        }

        // ---- O += P @ V (P from registers, V via trans-ldmatrix, split) ----
        #pragma unroll
        for (int kt4 = 0; kt4 < 4; kt4++) {
            uint32_t pah[4], pal[4];
            {
                const float* s0 = sacc[2 * kt4];
                const float* s1 = sacc[2 * kt4 + 1];
                float h00 = __bfloat162float(__float2bfloat16(s0[0]));
                float h01 = __bfloat162float(__float2bfloat16(s0[1]));
                float h02 = __bfloat162float(__float2bfloat16(s0[2]));
                float h03 = __bfloat162float(__float2bfloat16(s0[3]));
                float h10 = __bfloat162float(__float2bfloat16(s1[0]));
                float h11 = __bfloat162float(__float2bfloat16(s1[1]));
                float h12 = __bfloat162float(__float2bfloat16(s1[2]));
                float h13 = __bfloat162float(__float2bfloat16(s1[3]));
                pah[0] = packbf2(h00, h01); pah[1] = packbf2(h02, h03);
                pah[2] = packbf2(h10, h11); pah[3] = packbf2(h12, h13);
                pal[0] = packbf2(s0[0] - h00, s0[1] - h01);
                pal[1] = packbf2(s0[2] - h02, s0[3] - h03);
                pal[2] = packbf2(s1[0] - h10, s1[1] - h11);
                pal[3] = packbf2(s1[2] - h12, s1[3] - h13);
            }
            #pragma unroll
            for (int ntv = 0; ntv < 16; ntv++) {
                uint32_t bvh[2], bvl[2];
                const uint32_t voff =
                    SWZV((uint32_t)((kt4 * 16 + (l & 7) + ((l >> 3) & 1) * 8) * 256 + ntv * 16));
                ldmx2t(bvh, sb + FVH0 + voff);
                ldmx2t(bvl, sb + FVL0 + voff);
                mma16816(oacc[ntv], pah, bvh);
                mma16816(oacc[ntv], pah, bvl);
                mma16816(oacc[ntv], pal, bvh);
            }
        }
    }

    // ---- epilogue: normalize, emit bf16 hi/lo pairs [tok][h*128+dv] ----
    const float inv0 = 1.f / lsum[0];
    const float inv1 = 1.f / lsum[1];
    const size_t row0 = (size_t)(b * SS + r0) * ODIM + h * DV;
    const size_t row1 = (size_t)(b * SS + r1) * ODIM + h * DV;
    #pragma unroll
    for (int ntv = 0; ntv < 16; ntv++) {
        const int col = ntv * 8 + (l & 3) * 2;
        const float v00 = oacc[ntv][0] * inv0, v01 = oacc[ntv][1] * inv0;
        const float v10 = oacc[ntv][2] * inv1, v11 = oacc[ntv][3] * inv1;
        float h00 = __bfloat162float(__float2bfloat16(v00));
        float h01 = __bfloat162float(__float2bfloat16(v01));
        float h10 = __bfloat162float(__float2bfloat16(v10));
        float h11 = __bfloat162float(__float2bfloat16(v11));
        *reinterpret_cast<uint32_t*>(&ath[row0 + col]) = packbf2(h00, h01);
        *reinterpret_cast<uint32_t*>(&atl[row0 + col]) = packbf2(v00 - h00, v01 - h01);
        *reinterpret_cast<uint32_t*>(&ath[row1 + col]) = packbf2(h10, h11);
        *reinterpret_cast<uint32_t*>(&atl[row1 + col]) = packbf2(v10 - h10, v11 - h11);
    }
}

// ---------------- launch ----------------
extern "C" void kernel_launch(void* const* d_in, const int* in_sizes, int n_in,
                              void* d_out, int out_size)
{
    const float* hidden = (const float*)d_in[0];
    const float* qaw    = (const float*)d_in[1];
    const float* qaln   = (const float*)d_in[2];
    const float* qbw    = (const float*)d_in[3];
    const float* kvaw   = (const float*)d_in[4];
    const float* kvaln  = (const float*)d_in[5];
    const float* kvbw   = (const float*)d_in[6];
    const float* ow     = (const float*)d_in[7];
    const int*   pos    = (const int*)d_in[8];
    // d_in[9] = attention_mask (causal tril) — enforced analytically in flash kernel
    float* out = (float*)d_out;

    float *qc, *q, *ckv, *kv;
    bf16 *hidh, *hidl, *qawh, *qawl, *qbwh, *qbwl, *kvawh, *kvawl, *kvbwh, *kvbwl;
    bf16 *owh, *owl, *qch, *qcl, *cnh, *cnl, *ath, *atl;
    bf16 *Qhh, *Qhl, *Khh, *Khl, *Vhh, *Vhl;
    cudaGetSymbolAddress((void**)&qc,  g_qc);   cudaGetSymbolAddress((void**)&q,    g_q);
    cudaGetSymbolAddress((void**)&ckv, g_ckv);  cudaGetSymbolAddress((void**)&kv,   g_kv);
    cudaGetSymbolAddress((void**)&hidh, g_hidh); cudaGetSymbolAddress((void**)&hidl, g_hidl);
    cudaGetSymbolAddress((void**)&qawh, g_qawh); cudaGetSymbolAddress((void**)&qawl, g_qawl);
    cudaGetSymbolAddress((void**)&qbwh, g_qbwh); cudaGetSymbolAddress((void**)&qbwl, g_qbwl);
    cudaGetSymbolAddress((void**)&kvawh, g_kvawh); cudaGetSymbolAddress((void**)&kvawl, g_kvawl);
    cudaGetSymbolAddress((void**)&kvbwh, g_kvbwh); cudaGetSymbolAddress((void**)&kvbwl, g_kvbwl);
    cudaGetSymbolAddress((void**)&owh, g_owh);   cudaGetSymbolAddress((void**)&owl, g_owl);
    cudaGetSymbolAddress((void**)&qch, g_qch);   cudaGetSymbolAddress((void**)&qcl, g_qcl);
    cudaGetSymbolAddress((void**)&cnh, g_cnh);   cudaGetSymbolAddress((void**)&cnl, g_cnl);
    cudaGetSymbolAddress((void**)&ath, g_ath);   cudaGetSymbolAddress((void**)&atl, g_atl);
    cudaGetSymbolAddress((void**)&Qhh, g_Qhh);   cudaGetSymbolAddress((void**)&Qhl, g_Qhl);
    cudaGetSymbolAddress((void**)&Khh, g_Khh);   cudaGetSymbolAddress((void**)&Khl, g_Khl);
    cudaGetSymbolAddress((void**)&Vhh, g_Vhh);   cudaGetSymbolAddress((void**)&Vhl, g_Vhl);

    cudaFuncSetAttribute(gemm_tc,   cudaFuncAttributeMaxDynamicSharedMemorySize, GEMM_SMEM);
    cudaFuncSetAttribute(flashmma_k, cudaFuncAttributeMaxDynamicSharedMemorySize, FL_SMEM);

    #define CVT(x, h, l, n) cvt_pair_k<<<(unsigned)(((size_t)(n) + 255) / 256), 256>>>(x, h, l, (size_t)(n))
    CVT(hidden, hidh, hidl, (size_t)MTOK * HID);
    CVT(qaw,    qawh, qawl, (size_t)QRANK * HID);
    CVT(qbw,    qbwh, qbwl, (size_t)QBOUT * QRANK);
    CVT(kvbw,   kvbwh, kvbwl, (size_t)KVBOUT * KVRANK);
    CVT(ow,     owh,  owl,  (size_t)HID * ODIM);
    cvt_pad_k<<<(unsigned)(((size_t)KVAPAD * HID + 255) / 256), 256>>>(
        kvaw, kvawh, kvawl, KVAOUT, HID, KVAPAD);

    // 1) q_c = hidden @ q_a^T
    gemm_tc<<<dim3(QRANK/TN, MTOK/TM), 256, GEMM_SMEM>>>(hidh, hidl, qawh, qawl, qc, HID, QRANK);
    // 2) rmsnorm(q_c)
    rmsnorm_pair_k<<<MTOK, 256>>>(qc, qaln, qch, qcl, QRANK, QRANK);
    // 3) q = qcn @ q_b^T
    gemm_tc<<<dim3(QBOUT/TN, MTOK/TM), 256, GEMM_SMEM>>>(qch, qcl, qbwh, qbwl, q, QRANK, QBOUT);
    // 4) ckv = hidden @ kv_a^T (padded N)
    gemm_tc<<<dim3(KVAPAD/TN, MTOK/TM), 256, GEMM_SMEM>>>(hidh, hidl, kvawh, kvawl, ckv, HID, KVAPAD);
    // 5) rmsnorm(ckv[:, :512])
    rmsnorm_pair_k<<<MTOK, 256>>>(ckv, kvaln, cnh, cnl, KVRANK, KVAPAD);
    // 6) kv = cn @ kv_b^T
    gemm_tc<<<dim3(KVBOUT/TN, MTOK/TM), 256, GEMM_SMEM>>>(cnh, cnl, kvbwh, kvbwl, kv, KVRANK, KVBOUT);
    // 7) build bf16 split Q (rope+scale) and K,V
    build_q_k<<<dim3(SS, NH, BB), 128>>>(q, pos, Qhh, Qhl, rsqrtf((float)DQ));
    build_kv_k<<<dim3(SS, BB), 256>>>(ckv, kv, pos, Khh, Khl, Vhh, Vhl);
    // 8) HMMA flash attention -> attn (hi,lo) bf16
    flashmma_k<<<dim3(SS/FQM, BB*NH), 256, FL_SMEM>>>(Qhh, Qhl, Khh, Khl, Vhh, Vhl, ath, atl);
    // 9) out = attn @ o^T
    gemm_tc<<<dim3(HID/TN, MTOK/TM), 256, GEMM_SMEM>>>(ath, atl, owh, owl, out, ODIM, HID);
}

// round 10
// speedup vs baseline: 2.8754x; 1.1701x over previous
#include <cuda_runtime.h>
#include <cuda_bf16.h>
#include <math.h>
#include <stdint.h>

// ---------------- problem constants ----------------
#define BB 2
#define SS 2048
#define HID 5120
#define NH 32
#define DNOPE 128
#define DROPE 64
#define DV 128
#define DQ 192
#define QRANK 1536
#define KVRANK 512
#define MTOK (BB*SS)            // 4096
#define KVAOUT (KVRANK+DROPE)   // 576
#define KVAPAD 640              // padded to /128 for 128x128 tiles
#define QBOUT (NH*DQ)           // 6144
#define KVBOUT (NH*(DNOPE+DV))  // 8192
#define ODIM  (NH*DV)           // 4096

typedef __nv_bfloat16 bf16;

// ---------------- scratch (static device, allocation-free) ----------------
__device__ float g_qc  [(size_t)MTOK*QRANK];
__device__ float g_q   [(size_t)MTOK*QBOUT];
__device__ float g_ckv [(size_t)MTOK*KVAPAD];
__device__ float g_kv  [(size_t)MTOK*KVBOUT];
// bf16 hi/lo operand buffers (projections)
__device__ bf16 g_hidh[(size_t)MTOK*HID],   g_hidl[(size_t)MTOK*HID];
__device__ bf16 g_qawh[(size_t)QRANK*HID],  g_qawl[(size_t)QRANK*HID];
__device__ bf16 g_qbwh[(size_t)QBOUT*QRANK],g_qbwl[(size_t)QBOUT*QRANK];
__device__ bf16 g_kvawh[(size_t)KVAPAD*HID],g_kvawl[(size_t)KVAPAD*HID];
__device__ bf16 g_kvbwh[(size_t)KVBOUT*KVRANK], g_kvbwl[(size_t)KVBOUT*KVRANK];
__device__ bf16 g_owh [(size_t)HID*ODIM],   g_owl [(size_t)HID*ODIM];
__device__ bf16 g_qch [(size_t)MTOK*QRANK], g_qcl [(size_t)MTOK*QRANK];
__device__ bf16 g_cnh [(size_t)MTOK*KVRANK],g_cnl [(size_t)MTOK*KVRANK];
__device__ bf16 g_ath [(size_t)MTOK*ODIM],  g_atl [(size_t)MTOK*ODIM];
// bf16 hi/lo attention operands [b,h][s][*]
__device__ bf16 g_Qhh[(size_t)BB*NH*SS*DQ], g_Qhl[(size_t)BB*NH*SS*DQ];
__device__ bf16 g_Khh[(size_t)BB*NH*SS*DQ], g_Khl[(size_t)BB*NH*SS*DQ];
__device__ bf16 g_Vhh[(size_t)BB*NH*SS*DV], g_Vhl[(size_t)BB*NH*SS*DV];

// ---------------- warp-MMA helpers (plain sm_103-legal PTX) ----------------
__device__ __forceinline__ uint32_t s2u(const void* p) {
    uint32_t a;
    asm("{ .reg .u64 t; cvta.to.shared.u64 t, %1; cvt.u32.u64 %0, t; }" : "=r"(a) : "l"(p));
    return a;
}
#define SWZ128(off) ((off) ^ (((off) >> 3) & 0x70))   // 128B-row panels
#define SWZV(off)   ((off) ^ (((off) >> 4) & 0x70))   // 256B-row V panel

__device__ __forceinline__ void ldmx4(uint32_t r[4], uint32_t a) {
    asm volatile("ldmatrix.sync.aligned.m8n8.x4.shared.b16 {%0,%1,%2,%3}, [%4];"
        : "=r"(r[0]), "=r"(r[1]), "=r"(r[2]), "=r"(r[3]) : "r"(a));
}
__device__ __forceinline__ void ldmx2(uint32_t r[2], uint32_t a) {
    asm volatile("ldmatrix.sync.aligned.m8n8.x2.shared.b16 {%0,%1}, [%2];"
        : "=r"(r[0]), "=r"(r[1]) : "r"(a));
}
__device__ __forceinline__ void ldmx2t(uint32_t r[2], uint32_t a) {
    asm volatile("ldmatrix.sync.aligned.m8n8.x2.trans.shared.b16 {%0,%1}, [%2];"
        : "=r"(r[0]), "=r"(r[1]) : "r"(a));
}
__device__ __forceinline__ void mma16816(float c[4], const uint32_t a[4], const uint32_t b[2]) {
    asm volatile(
        "mma.sync.aligned.m16n8k16.row.col.f32.bf16.bf16.f32 "
        "{%0,%1,%2,%3}, {%4,%5,%6,%7}, {%8,%9}, {%0,%1,%2,%3};"
        : "+f"(c[0]), "+f"(c[1]), "+f"(c[2]), "+f"(c[3])
        : "r"(a[0]), "r"(a[1]), "r"(a[2]), "r"(a[3]), "r"(b[0]), "r"(b[1]));
}
__device__ __forceinline__ uint32_t packbf2(float lo, float hi) {
    __nv_bfloat162 t = __floats2bfloat162_rn(lo, hi);
    return *reinterpret_cast<uint32_t*>(&t);
}
__device__ __forceinline__ void cpa16(uint32_t dst, const void* src) {
    asm volatile("cp.async.cg.shared.global [%0], [%1], 16;" :: "r"(dst), "l"(src));
}
#define CPA_COMMIT() asm volatile("cp.async.commit_group;" ::: "memory")
#define CPA_WAIT1()  asm volatile("cp.async.wait_group 1;" ::: "memory")
#define CPA_WAIT0()  asm volatile("cp.async.wait_group 0;" ::: "memory")

// ===== split-bf16 HMMA GEMM, 2-stage cp.async pipeline =====
// C[m,n] = sum_k A[m,k]*B[n,k]; A,B as (hi,lo) bf16 pairs. M,N %128; K %64.
#define TM 128
#define TN 128
#define TKC 64
#define TILE_B 16384
#define SM_AH 0
#define SM_AL 16384
#define SM_BH 32768
#define SM_BL 49152
#define STG_B 65536
#define GEMM_SMEM (2 * STG_B)   // 131072

__global__ __launch_bounds__(256, 1)
void gemm_tc(const bf16* __restrict__ Ah, const bf16* __restrict__ Al,
             const bf16* __restrict__ Bh, const bf16* __restrict__ Bl,
             float* __restrict__ C, int K, int ldc)
{
    extern __shared__ char smem[];
    const uint32_t sb = s2u(smem);
    const int tid = threadIdx.x, wid = tid >> 5, lid = tid & 31;
    const int m0 = blockIdx.y * TM, n0 = blockIdx.x * TN;
    const int wm = wid & 1, wn = wid >> 1;

    const int grow = tid >> 1;
    const int half = tid & 1;
    const uint4* rAh = reinterpret_cast<const uint4*>(Ah + (size_t)(m0 + grow) * K);
    const uint4* rAl = reinterpret_cast<const uint4*>(Al + (size_t)(m0 + grow) * K);
    const uint4* rBh = reinterpret_cast<const uint4*>(Bh + (size_t)(n0 + grow) * K);
    const uint4* rBl = reinterpret_cast<const uint4*>(Bl + (size_t)(n0 + grow) * K);

    uint32_t soff[4];
    #pragma unroll
    for (int j = 0; j < 4; j++)
        soff[j] = SWZ128((uint32_t)(grow * 128 + half * 64 + j * 16));

    float c[4][4][4];
    #pragma unroll
    for (int mt = 0; mt < 4; mt++)
        #pragma unroll
        for (int nt = 0; nt < 4; nt++)
            #pragma unroll
            for (int e = 0; e < 4; e++) c[mt][nt][e] = 0.f;

    const int arow = wm * 64 + (lid & 15);
    const int aq   = lid >> 4;
    const int brow = wn * 32 + (lid & 7);
    const int bq   = (lid >> 3) & 1;

    // prologue: stage 0 loads for chunk 0
    {
        const int base = half * 4;
        #pragma unroll
        for (int j = 0; j < 4; j++) {
            cpa16(sb + SM_AH + soff[j], rAh + base + j);
            cpa16(sb + SM_AL + soff[j], rAl + base + j);
            cpa16(sb + SM_BH + soff[j], rBh + base + j);
            cpa16(sb + SM_BL + soff[j], rBl + base + j);
        }
        CPA_COMMIT();
    }

    const int nch = K / TKC;
    for (int ch = 0; ch < nch; ch++) {
        const uint32_t scur = sb + (uint32_t)(ch & 1) * STG_B;
        if (ch + 1 < nch) {
            const uint32_t snxt = sb + (uint32_t)((ch + 1) & 1) * STG_B;
            const int base = (ch + 1) * (TKC / 8) + half * 4;
            #pragma unroll
            for (int j = 0; j < 4; j++) {
                cpa16(snxt + SM_AH + soff[j], rAh + base + j);
                cpa16(snxt + SM_AL + soff[j], rAl + base + j);
                cpa16(snxt + SM_BH + soff[j], rBh + base + j);
                cpa16(snxt + SM_BL + soff[j], rBl + base + j);
            }
            CPA_COMMIT();
            CPA_WAIT1();
        } else {
            CPA_WAIT0();
        }
        __syncthreads();

        #pragma unroll
        for (int ks = 0; ks < 4; ks++) {
            uint32_t ah[4][4], al[4][4], bh[4][2], bl[4][2];
            #pragma unroll
            for (int mt = 0; mt < 4; mt++) {
                const uint32_t off = SWZ128((uint32_t)((arow + mt * 16) * 128 + (ks * 2 + aq) * 16));
                ldmx4(ah[mt], scur + SM_AH + off);
                ldmx4(al[mt], scur + SM_AL + off);
            }
            #pragma unroll
            for (int nt = 0; nt < 4; nt++) {
                const uint32_t off = SWZ128((uint32_t)((brow + nt * 8) * 128 + (ks * 2 + bq) * 16));
                ldmx2(bh[nt], scur + SM_BH + off);
                ldmx2(bl[nt], scur + SM_BL + off);
            }
            #pragma unroll
            for (int mt = 0; mt < 4; mt++)
                #pragma unroll
                for (int nt = 0; nt < 4; nt++) {
                    mma16816(c[mt][nt], ah[mt], bh[nt]);
                    mma16816(c[mt][nt], ah[mt], bl[nt]);
                    mma16816(c[mt][nt], al[mt], bh[nt]);
                }
        }
        __syncthreads();
    }

    const int mbase = m0 + wm * 64 + (lid >> 2);
    const int nbase = n0 + wn * 32 + (lid & 3) * 2;
    #pragma unroll
    for (int mt = 0; mt < 4; mt++)
        #pragma unroll
        for (int nt = 0; nt < 4; nt++) {
            float* p0 = C + (size_t)(mbase + mt * 16) * ldc + nbase + nt * 8;
            float* p1 = p0 + 8 * ldc;
            *reinterpret_cast<float2*>(p0) = make_float2(c[mt][nt][0], c[mt][nt][1]);
            *reinterpret_cast<float2*>(p1) = make_float2(c[mt][nt][2], c[mt][nt][3]);
        }
}

// ---------------- fp32 -> (hi,lo) bf16 conversions ----------------
__global__ __launch_bounds__(256)
void cvt_pair_k(const float* __restrict__ x, bf16* __restrict__ h,
                bf16* __restrict__ l, size_t n)
{
    const size_t i = (size_t)blockIdx.x * 256 + threadIdx.x;
    if (i >= n) return;
    const float v = x[i];
    const bf16 hh = __float2bfloat16(v);
    h[i] = hh;
    l[i] = __float2bfloat16(v - __bfloat162float(hh));
}

__global__ __launch_bounds__(256)
void cvt_pad_k(const float* __restrict__ x, bf16* __restrict__ h,
               bf16* __restrict__ l, int rows, int cols, int padrows)
{
    const size_t i = (size_t)blockIdx.x * 256 + threadIdx.x;
    if (i >= (size_t)padrows * cols) return;
    const int r = (int)(i / cols);
    const float v = (r < rows) ? x[i] : 0.f;
    const bf16 hh = __float2bfloat16(v);
    h[i] = hh;
    l[i] = __float2bfloat16(v - __bfloat162float(hh));
}

// ---------------- RMSNorm -> (hi,lo) bf16 ----------------
__global__ __launch_bounds__(256)
void rmsnorm_pair_k(const float* __restrict__ x, const float* __restrict__ w,
                    bf16* __restrict__ yh, bf16* __restrict__ yl,
                    int n, int in_stride)
{
    const int row = blockIdx.x;
    const float* xr = x + (size_t)row * in_stride;
    bf16* yhr = yh + (size_t)row * n;
    bf16* ylr = yl + (size_t)row * n;
    __shared__ float red[256];
    float s = 0.f;
    for (int i = threadIdx.x; i < n; i += 256) { float v = xr[i]; s += v * v; }
    red[threadIdx.x] = s; __syncthreads();
    for (int o = 128; o; o >>= 1) {
        if (threadIdx.x < o) red[threadIdx.x] += red[threadIdx.x + o];
        __syncthreads();
    }
    const float r = rsqrtf(red[0] / n + 1e-6f);
    for (int i = threadIdx.x; i < n; i += 256) {
        const float v = xr[i] * r * w[i];
        const bf16 hh = __float2bfloat16(v);
        yhr[i] = hh;
        ylr[i] = __float2bfloat16(v - __bfloat162float(hh));
    }
}

// ------- build Q (RoPE + scale) -> bf16 hi/lo [b,h,s,192] -------
__global__ __launch_bounds__(128)
void build_q_k(const float* __restrict__ q, const int* __restrict__ pos,
               bf16* __restrict__ Qhh, bf16* __restrict__ Qhl, float scale)
{
    const int s = blockIdx.x, h = blockIdx.y, b = blockIdx.z;
    const float* in = q + ((size_t)(b * SS + s)) * QBOUT + h * DQ;
    const size_t ob = (((size_t)(b * NH + h) * SS) + s) * DQ;
    const int t = threadIdx.x;
    {
        const float v = in[t] * scale;
        const bf16 hh = __float2bfloat16(v);
        Qhh[ob + t] = hh;
        Qhl[ob + t] = __float2bfloat16(v - __bfloat162float(hh));
    }
    if (t < 32) {
        const float tp = (float)pos[b * SS + s];
        const float f = exp2f((float)t * (-13.2877123795494f / 32.f));
        float c, sn; sincosf(tp * f, &sn, &c);
        const float x0 = in[DNOPE + 2 * t];
        const float x1 = in[DNOPE + 2 * t + 1];
        const float v0 = (x0 * c - x1 * sn) * scale;
        const float v1 = (x1 * c + x0 * sn) * scale;
        bf16 h0 = __float2bfloat16(v0), h1 = __float2bfloat16(v1);
        Qhh[ob + DNOPE + t]      = h0;
        Qhl[ob + DNOPE + t]      = __float2bfloat16(v0 - __bfloat162float(h0));
        Qhh[ob + DNOPE + 32 + t] = h1;
        Qhl[ob + DNOPE + 32 + t] = __float2bfloat16(v1 - __bfloat162float(h1));
    }
}

// ------- build K,V -> bf16 hi/lo [b,h,s,*] -------
__global__ __launch_bounds__(256)
void build_kv_k(const float* __restrict__ ckv, const float* __restrict__ kv,
                const int* __restrict__ pos,
                bf16* __restrict__ Khh, bf16* __restrict__ Khl,
                bf16* __restrict__ Vhh, bf16* __restrict__ Vhl)
{
    const int s = blockIdx.x, b = blockIdx.y;
    const size_t bs = (size_t)b * SS + s;
    __shared__ float kr[DROPE];
    const int tid = threadIdx.x;
    if (tid < 32) {
        const float tp = (float)pos[bs];
        const float f = exp2f((float)tid * (-13.2877123795494f / 32.f));
        float c, sn; sincosf(tp * f, &sn, &c);
        const float x0 = ckv[bs * KVAPAD + KVRANK + 2 * tid];
        const float x1 = ckv[bs * KVAPAD + KVRANK + 2 * tid + 1];
        kr[tid]      = x0 * c - x1 * sn;
        kr[32 + tid] = x1 * c + x0 * sn;
    }
    __syncthreads();
    const float* kvrow = kv + bs * KVBOUT;
    for (int idx = tid; idx < NH * DQ; idx += 256) {
        const int h = idx / DQ, d = idx % DQ;
        const float v = (d < DNOPE) ? kvrow[h * (DNOPE + DV) + d] : kr[d - DNOPE];
        const size_t o = (((size_t)(b * NH + h) * SS) + s) * DQ + d;
        const bf16 hh = __float2bfloat16(v);
        Khh[o] = hh;
        Khl[o] = __float2bfloat16(v - __bfloat162float(hh));
    }
    for (int idx = tid; idx < NH * DV; idx += 256) {
        const int h = idx / DV, d = idx % DV;
        const float v = kvrow[h * (DNOPE + DV) + DNOPE + d];
        const size_t o = (((size_t)(b * NH + h) * SS) + s) * DV + d;
        const bf16 hh = __float2bfloat16(v);
        Vhh[o] = hh;
        Vhl[o] = __float2bfloat16(v - __bfloat162float(hh));
    }
}

// ====== HMMA flash attention: 128 q-rows/CTA, 64-key tiles, split bf16 ======
#define FQM 128
#define FKN 64
#define FQH0 0
#define FQL0 49152
#define FKH0 98304
#define FKL0 122880
#define FVH0 147456
#define FVL0 163840
#define FL_SMEM 180224

__global__ __launch_bounds__(256, 1)
void flashmma_k(const bf16* __restrict__ Qhh, const bf16* __restrict__ Qhl,
                const bf16* __restrict__ Khh, const bf16* __restrict__ Khl,
                const bf16* __restrict__ Vhh, const bf16* __restrict__ Vhl,
                bf16* __restrict__ ath, bf16* __restrict__ atl)
{
    extern __shared__ char sm[];
    const uint32_t sb = s2u(sm);
    const int tid = threadIdx.x, w = tid >> 5, l = tid & 31;
    const int qt = blockIdx.x, bh = blockIdx.y;
    const int b = bh / NH, h = bh % NH;
    const int q0 = qt * FQM;

    const uint4* Qh4 = reinterpret_cast<const uint4*>(Qhh + ((size_t)bh * SS + q0) * DQ);
    const uint4* Ql4 = reinterpret_cast<const uint4*>(Qhl + ((size_t)bh * SS + q0) * DQ);
    for (int idx = tid; idx < 128 * 24; idx += 256) {
        const int row = idx / 24, u = idx % 24;
        const int p = u >> 3, qd = u & 7;
        const uint32_t off = (uint32_t)(p * 16384) + SWZ128((uint32_t)(row * 128 + qd * 16));
        *reinterpret_cast<uint4*>(sm + FQH0 + off) = Qh4[row * 24 + u];
        *reinterpret_cast<uint4*>(sm + FQL0 + off) = Ql4[row * 24 + u];
    }

    float oacc[16][4];
    #pragma unroll
    for (int i = 0; i < 16; i++)
        #pragma unroll
        for (int e = 0; e < 4; e++) oacc[i][e] = 0.f;
    float mrow[2] = {-1e30f, -1e30f};
    float lsum[2] = {0.f, 0.f};

    const int r0 = q0 + w * 16 + (l >> 2);
    const int r1 = r0 + 8;

    const int ktmax = 2 * qt + 1;
    for (int kt = 0; kt <= ktmax; kt++) {
        const int k0 = kt * FKN;
        __syncthreads();
        const uint4* Kh4 = reinterpret_cast<const uint4*>(Khh + ((size_t)bh * SS + k0) * DQ);
        const uint4* Kl4 = reinterpret_cast<const uint4*>(Khl + ((size_t)bh * SS + k0) * DQ);
        const uint4* Vh4 = reinterpret_cast<const uint4*>(Vhh + ((size_t)bh * SS + k0) * DV);
        const uint4* Vl4 = reinterpret_cast<const uint4*>(Vhl + ((size_t)bh * SS + k0) * DV);
        for (int idx = tid; idx < 64 * 24; idx += 256) {
            const int row = idx / 24, u = idx % 24;
            const int p = u >> 3, qd = u & 7;
            const uint32_t off = (uint32_t)(p * 8192) + SWZ128((uint32_t)(row * 128 + qd * 16));
            *reinterpret_cast<uint4*>(sm + FKH0 + off) = Kh4[row * 24 + u];
            *reinterpret_cast<uint4*>(sm + FKL0 + off) = Kl4[row * 24 + u];
        }
        for (int idx = tid; idx < 64 * 16; idx += 256) {
            const int row = idx >> 4, qd = idx & 15;
            const uint32_t off = SWZV((uint32_t)(row * 256 + qd * 16));
            *reinterpret_cast<uint4*>(sm + FVH0 + off) = Vh4[row * 16 + qd];
            *reinterpret_cast<uint4*>(sm + FVL0 + off) = Vl4[row * 16 + qd];
        }
        __syncthreads();

        float sacc[8][4];
        #pragma unroll
        for (int nt = 0; nt < 8; nt++)
            #pragma unroll
            for (int e = 0; e < 4; e++) sacc[nt][e] = 0.f;

        #pragma unroll
        for (int p = 0; p < 3; p++)
            #pragma unroll
            for (int ks = 0; ks < 4; ks++) {
                uint32_t ah[4], al[4];
                const uint32_t aoff = (uint32_t)(p * 16384) +
                    SWZ128((uint32_t)((w * 16 + (l & 15)) * 128 + (ks * 2 + (l >> 4)) * 16));
                ldmx4(ah, sb + FQH0 + aoff);
                ldmx4(al, sb + FQL0 + aoff);
                #pragma unroll
                for (int nt = 0; nt < 8; nt++) {
                    uint32_t bh_[2], bl_[2];
                    const uint32_t boff = (uint32_t)(p * 8192) +
                        SWZ128((uint32_t)((nt * 8 + (l & 7)) * 128 + (ks * 2 + ((l >> 3) & 1)) * 16));
                    ldmx2(bh_, sb + FKH0 + boff);
                    ldmx2(bl_, sb + FKL0 + boff);
                    mma16816(sacc[nt], ah, bh_);
                    mma16816(sacc[nt], ah, bl_);
                    mma16816(sacc[nt], al, bh_);
                }
            }

        if (kt >= 2 * qt) {
            #pragma unroll
            for (int nt = 0; nt < 8; nt++) {
                const int c0 = k0 + nt * 8 + (l & 3) * 2;
                if (c0     > r0) sacc[nt][0] = -1e30f;
                if (c0 + 1 > r0) sacc[nt][1] = -1e30f;
                if (c0     > r1) sacc[nt][2] = -1e30f;
                if (c0 + 1 > r1) sacc[nt][3] = -1e30f;
            }
        }

        float alpha[2];
        #pragma unroll
        for (int sub = 0; sub < 2; sub++) {
            float tm = -1e30f;
            #pragma unroll
            for (int nt = 0; nt < 8; nt++)
                tm = fmaxf(tm, fmaxf(sacc[nt][2 * sub], sacc[nt][2 * sub + 1]));
            tm = fmaxf(tm, __shfl_xor_sync(0xffffffffu, tm, 1));
            tm = fmaxf(tm, __shfl_xor_sync(0xffffffffu, tm, 2));
            const float mn = fmaxf(mrow[sub], tm);
            alpha[sub] = __expf(mrow[sub] - mn);
            float rs = 0.f;
            #pragma unroll
            for (int nt = 0; nt < 8; nt++) {
                sacc[nt][2 * sub]     = __expf(sacc[nt][2 * sub] - mn);
                sacc[nt][2 * sub + 1] = __expf(sacc[nt][2 * sub + 1] - mn);
                rs += sacc[nt][2 * sub] + sacc[nt][2 * sub + 1];
            }
            rs += __shfl_xor_sync(0xffffffffu, rs, 1);
            rs += __shfl_xor_sync(0xffffffffu, rs, 2);
            lsum[sub] = lsum[sub] * alpha[sub] + rs;
            mrow[sub] = mn;
        }
        #pragma unroll
        for (int ntv = 0; ntv < 16; ntv++) {
            oacc[ntv][0] *= alpha[0]; oacc[ntv][1] *= alpha[0];
            oacc[ntv][2] *= alpha[1]; oacc[ntv][3] *= alpha[1];
        }

        #pragma unroll
        for (int kt4 = 0; kt4 < 4; kt4++) {
            uint32_t pah[4], pal[4];
            {
                const float* s0 = sacc[2 * kt4];
                const float* s1 = sacc[2 * kt4 + 1];
                float h00 = __bfloat162float(__float2bfloat16(s0[0]));
                float h01 = __bfloat162float(__float2bfloat16(s0[1]));
                float h02 = __bfloat162float(__float2bfloat16(s0[2]));
                float h03 = __bfloat162float(__float2bfloat16(s0[3]));
                float h10 = __bfloat162float(__float2bfloat16(s1[0]));
                float h11 = __bfloat162float(__float2bfloat16(s1[1]));
                float h12 = __bfloat162float(__float2bfloat16(s1[2]));
                float h13 = __bfloat162float(__float2bfloat16(s1[3]));
                pah[0] = packbf2(h00, h01); pah[1] = packbf2(h02, h03);
                pah[2] = packbf2(h10, h11); pah[3] = packbf2(h12, h13);
                pal[0] = packbf2(s0[0] - h00, s0[1] - h01);
                pal[1] = packbf2(s0[2] - h02, s0[3] - h03);
                pal[2] = packbf2(s1[0] - h10, s1[1] - h11);
                pal[3] = packbf2(s1[2] - h12, s1[3] - h13);
            }
            #pragma unroll
            for (int ntv = 0; ntv < 16; ntv++) {
                uint32_t bvh[2], bvl[2];
                const uint32_t voff =
                    SWZV((uint32_t)((kt4 * 16 + (l & 7) + ((l >> 3) & 1) * 8) * 256 + ntv * 16));
                ldmx2t(bvh, sb + FVH0 + voff);
                ldmx2t(bvl, sb + FVL0 + voff);
                mma16816(oacc[ntv], pah, bvh);
                mma16816(oacc[ntv], pah, bvl);
                mma16816(oacc[ntv], pal, bvh);
            }
        }
    }

    const float inv0 = 1.f / lsum[0];
    const float inv1 = 1.f / lsum[1];
    const size_t row0 = (size_t)(b * SS + r0) * ODIM + h * DV;
    const size_t row1 = (size_t)(b * SS + r1) * ODIM + h * DV;
    #pragma unroll
    for (int ntv = 0; ntv < 16; ntv++) {
        const int col = ntv * 8 + (l & 3) * 2;
        const float v00 = oacc[ntv][0] * inv0, v01 = oacc[ntv][1] * inv0;
        const float v10 = oacc[ntv][2] * inv1, v11 = oacc[ntv][3] * inv1;
        float h00 = __bfloat162float(__float2bfloat16(v00));
        float h01 = __bfloat162float(__float2bfloat16(v01));
        float h10 = __bfloat162float(__float2bfloat16(v10));
        float h11 = __bfloat162float(__float2bfloat16(v11));
        *reinterpret_cast<uint32_t*>(&ath[row0 + col]) = packbf2(h00, h01);
        *reinterpret_cast<uint32_t*>(&atl[row0 + col]) = packbf2(v00 - h00, v01 - h01);
        *reinterpret_cast<uint32_t*>(&ath[row1 + col]) = packbf2(h10, h11);
        *reinterpret_cast<uint32_t*>(&atl[row1 + col]) = packbf2(v10 - h10, v11 - h11);
    }
}

// ---------------- launch ----------------
extern "C" void kernel_launch(void* const* d_in, const int* in_sizes, int n_in,
                              void* d_out, int out_size)
{
    const float* hidden = (const float*)d_in[0];
    const float* qaw    = (const float*)d_in[1];
    const float* qaln   = (const float*)d_in[2];
    const float* qbw    = (const float*)d_in[3];
    const float* kvaw   = (const float*)d_in[4];
    const float* kvaln  = (const float*)d_in[5];
    const float* kvbw   = (const float*)d_in[6];
    const float* ow     = (const float*)d_in[7];
    const int*   pos    = (const int*)d_in[8];
    // d_in[9] = attention_mask (causal tril) — enforced analytically in flash kernel
    float* out = (float*)d_out;

    float *qc, *q, *ckv, *kv;
    bf16 *hidh, *hidl, *qawh, *qawl, *qbwh, *qbwl, *kvawh, *kvawl, *kvbwh, *kvbwl;
    bf16 *owh, *owl, *qch, *qcl, *cnh, *cnl, *ath, *atl;
    bf16 *Qhh, *Qhl, *Khh, *Khl, *Vhh, *Vhl;
    cudaGetSymbolAddress((void**)&qc,  g_qc);   cudaGetSymbolAddress((void**)&q,    g_q);
    cudaGetSymbolAddress((void**)&ckv, g_ckv);  cudaGetSymbolAddress((void**)&kv,   g_kv);
    cudaGetSymbolAddress((void**)&hidh, g_hidh); cudaGetSymbolAddress((void**)&hidl, g_hidl);
    cudaGetSymbolAddress((void**)&qawh, g_qawh); cudaGetSymbolAddress((void**)&qawl, g_qawl);
    cudaGetSymbolAddress((void**)&qbwh, g_qbwh); cudaGetSymbolAddress((void**)&qbwl, g_qbwl);
    cudaGetSymbolAddress((void**)&kvawh, g_kvawh); cudaGetSymbolAddress((void**)&kvawl, g_kvawl);
    cudaGetSymbolAddress((void**)&kvbwh, g_kvbwh); cudaGetSymbolAddress((void**)&kvbwl, g_kvbwl);
    cudaGetSymbolAddress((void**)&owh, g_owh);   cudaGetSymbolAddress((void**)&owl, g_owl);
    cudaGetSymbolAddress((void**)&qch, g_qch);   cudaGetSymbolAddress((void**)&qcl, g_qcl);
    cudaGetSymbolAddress((void**)&cnh, g_cnh);   cudaGetSymbolAddress((void**)&cnl, g_cnl);
    cudaGetSymbolAddress((void**)&ath, g_ath);   cudaGetSymbolAddress((void**)&atl, g_atl);
    cudaGetSymbolAddress((void**)&Qhh, g_Qhh);   cudaGetSymbolAddress((void**)&Qhl, g_Qhl);
    cudaGetSymbolAddress((void**)&Khh, g_Khh);   cudaGetSymbolAddress((void**)&Khl, g_Khl);
    cudaGetSymbolAddress((void**)&Vhh, g_Vhh);   cudaGetSymbolAddress((void**)&Vhl, g_Vhl);

    cudaFuncSetAttribute(gemm_tc,    cudaFuncAttributeMaxDynamicSharedMemorySize, GEMM_SMEM);
    cudaFuncSetAttribute(flashmma_k, cudaFuncAttributeMaxDynamicSharedMemorySize, FL_SMEM);

    #define CVT(x, h, l, n) cvt_pair_k<<<(unsigned)(((size_t)(n) + 255) / 256), 256>>>(x, h, l, (size_t)(n))
    CVT(hidden, hidh, hidl, (size_t)MTOK * HID);
    CVT(qaw,    qawh, qawl, (size_t)QRANK * HID);
    CVT(qbw,    qbwh, qbwl, (size_t)QBOUT * QRANK);
    CVT(kvbw,   kvbwh, kvbwl, (size_t)KVBOUT * KVRANK);
    CVT(ow,     owh,  owl,  (size_t)HID * ODIM);
    cvt_pad_k<<<(unsigned)(((size_t)KVAPAD * HID + 255) / 256), 256>>>(
        kvaw, kvawh, kvawl, KVAOUT, HID, KVAPAD);

    // 1) q_c = hidden @ q_a^T
    gemm_tc<<<dim3(QRANK/TN, MTOK/TM), 256, GEMM_SMEM>>>(hidh, hidl, qawh, qawl, qc, HID, QRANK);
    // 2) rmsnorm(q_c)
    rmsnorm_pair_k<<<MTOK, 256>>>(qc, qaln, qch, qcl, QRANK, QRANK);
    // 3) q = qcn @ q_b^T
    gemm_tc<<<dim3(QBOUT/TN, MTOK/TM), 256, GEMM_SMEM>>>(qch, qcl, qbwh, qbwl, q, QRANK, QBOUT);
    // 4) ckv = hidden @ kv_a^T (padded N)
    gemm_tc<<<dim3(KVAPAD/TN, MTOK/TM), 256, GEMM_SMEM>>>(hidh, hidl, kvawh, kvawl, ckv, HID, KVAPAD);
    // 5) rmsnorm(ckv[:, :512])
    rmsnorm_pair_k<<<MTOK, 256>>>(ckv, kvaln, cnh, cnl, KVRANK, KVAPAD);
    // 6) kv = cn @ kv_b^T
    gemm_tc<<<dim3(KVBOUT/TN, MTOK/TM), 256, GEMM_SMEM>>>(cnh, cnl, kvbwh, kvbwl, kv, KVRANK, KVBOUT);
    // 7) build bf16 split Q (rope+scale) and K,V
    build_q_k<<<dim3(SS, NH, BB), 128>>>(q, pos, Qhh, Qhl, rsqrtf((float)DQ));
    build_kv_k<<<dim3(SS, BB), 256>>>(ckv, kv, pos, Khh, Khl, Vhh, Vhl);
    // 8) HMMA flash attention -> attn (hi,lo) bf16
    flashmma_k<<<dim3(SS/FQM, BB*NH), 256, FL_SMEM>>>(Qhh, Qhl, Khh, Khl, Vhh, Vhl, ath, atl);
    // 9) out = attn @ o^T
    gemm_tc<<<dim3(HID/TN, MTOK/TM), 256, GEMM_SMEM>>>(ath, atl, owh, owl, out, ODIM, HID);
}

// round 12
// speedup vs baseline: 3.3677x; 1.1712x over previous
#include <cuda_runtime.h>
#include <cuda_bf16.h>
#include <math.h>
#include <stdint.h>

// ---------------- problem constants ----------------
#define BB 2
#define SS 2048
#define HID 5120
#define NH 32
#define DNOPE 128
#define DROPE 64
#define DV 128
#define DQ 192
#define QRANK 1536
#define KVRANK 512
#define MTOK (BB*SS)            // 4096
#define KVAOUT (KVRANK+DROPE)   // 576
#define KVAPAD 640              // kv_a rows padded to /128
#define W1R (QRANK+KVAPAD)      // 2176 combined q_a+kv_a output dim
#define QBOUT (NH*DQ)           // 6144
#define KVBOUT (NH*(DNOPE+DV))  // 8192
#define ODIM  (NH*DV)           // 4096

typedef __nv_bfloat16 bf16;

// ---------------- scratch (static device, allocation-free) ----------------
__device__ float g_c1  [(size_t)MTOK*W1R];     // [q_c | ckv] combined
__device__ float g_q   [(size_t)MTOK*QBOUT];
__device__ float g_kv  [(size_t)MTOK*KVBOUT];
// bf16 hi/lo operand buffers (projections)
__device__ bf16 g_hidh[(size_t)MTOK*HID],   g_hidl[(size_t)MTOK*HID];
__device__ bf16 g_w1h [(size_t)W1R*HID],    g_w1l [(size_t)W1R*HID];   // [qaw ; kvaw(pad)]
__device__ bf16 g_qbwh[(size_t)QBOUT*QRANK],g_qbwl[(size_t)QBOUT*QRANK];
__device__ bf16 g_kvbwh[(size_t)KVBOUT*KVRANK], g_kvbwl[(size_t)KVBOUT*KVRANK];
__device__ bf16 g_owh [(size_t)HID*ODIM],   g_owl [(size_t)HID*ODIM];
__device__ bf16 g_qch [(size_t)MTOK*QRANK], g_qcl [(size_t)MTOK*QRANK];
__device__ bf16 g_cnh [(size_t)MTOK*KVRANK],g_cnl [(size_t)MTOK*KVRANK];
__device__ bf16 g_ath [(size_t)MTOK*ODIM],  g_atl [(size_t)MTOK*ODIM];
// bf16 hi/lo attention operands [b,h][s][*]
__device__ bf16 g_Qhh[(size_t)BB*NH*SS*DQ], g_Qhl[(size_t)BB*NH*SS*DQ];
__device__ bf16 g_Khh[(size_t)BB*NH*SS*DQ], g_Khl[(size_t)BB*NH*SS*DQ];
__device__ bf16 g_Vhh[(size_t)BB*NH*SS*DV], g_Vhl[(size_t)BB*NH*SS*DV];

// ---------------- warp-MMA helpers (plain sm_103-legal PTX) ----------------
__device__ __forceinline__ uint32_t s2u(const void* p) {
    uint32_t a;
    asm("{ .reg .u64 t; cvta.to.shared.u64 t, %1; cvt.u32.u64 %0, t; }" : "=r"(a) : "l"(p));
    return a;
}
#define SWZ128(off) ((off) ^ (((off) >> 3) & 0x70))   // 128B-row panels
#define SWZV(off)   ((off) ^ (((off) >> 4) & 0x70))   // 256B-row V panel

__device__ __forceinline__ void ldmx4(uint32_t r[4], uint32_t a) {
    asm volatile("ldmatrix.sync.aligned.m8n8.x4.shared.b16 {%0,%1,%2,%3}, [%4];"
        : "=r"(r[0]), "=r"(r[1]), "=r"(r[2]), "=r"(r[3]) : "r"(a));
}
__device__ __forceinline__ void ldmx2(uint32_t r[2], uint32_t a) {
    asm volatile("ldmatrix.sync.aligned.m8n8.x2.shared.b16 {%0,%1}, [%2];"
        : "=r"(r[0]), "=r"(r[1]) : "r"(a));
}
__device__ __forceinline__ void ldmx2t(uint32_t r[2], uint32_t a) {
    asm volatile("ldmatrix.sync.aligned.m8n8.x2.trans.shared.b16 {%0,%1}, [%2];"
        : "=r"(r[0]), "=r"(r[1]) : "r"(a));
}
__device__ __forceinline__ void mma16816(float c[4], const uint32_t a[4], const uint32_t b[2]) {
    asm volatile(
        "mma.sync.aligned.m16n8k16.row.col.f32.bf16.bf16.f32 "
        "{%0,%1,%2,%3}, {%4,%5,%6,%7}, {%8,%9}, {%0,%1,%2,%3};"
        : "+f"(c[0]), "+f"(c[1]), "+f"(c[2]), "+f"(c[3])
        : "r"(a[0]), "r"(a[1]), "r"(a[2]), "r"(a[3]), "r"(b[0]), "r"(b[1]));
}
__device__ __forceinline__ uint32_t packbf2(float lo, float hi) {
    __nv_bfloat162 t = __floats2bfloat162_rn(lo, hi);
    return *reinterpret_cast<uint32_t*>(&t);
}
__device__ __forceinline__ void cpa16(uint32_t dst, const void* src) {
    asm volatile("cp.async.cg.shared.global [%0], [%1], 16;" :: "r"(dst), "l"(src));
}
#define CPA_COMMIT() asm volatile("cp.async.commit_group;" ::: "memory")
#define CPA_WAIT1()  asm volatile("cp.async.wait_group 1;" ::: "memory")
#define CPA_WAIT0()  asm volatile("cp.async.wait_group 0;" ::: "memory")

// ===== split-bf16 HMMA GEMM, 2-stage cp.async pipeline, 1 barrier/chunk =====
// C[m,n] = sum_k A[m,k]*B[n,k]; A,B as (hi,lo) bf16 pairs. M,N %128; K %64.
#define TM 128
#define TN 128
#define TKC 64
#define SM_AH 0
#define SM_AL 16384
#define SM_BH 32768
#define SM_BL 49152
#define STG_B 65536
#define GEMM_SMEM (2 * STG_B)   // 131072

__global__ __launch_bounds__(256, 1)
void gemm_tc(const bf16* __restrict__ Ah, const bf16* __restrict__ Al,
             const bf16* __restrict__ Bh, const bf16* __restrict__ Bl,
             float* __restrict__ C, int K, int ldc)
{
    extern __shared__ char smem[];
    const uint32_t sb = s2u(smem);
    const int tid = threadIdx.x, wid = tid >> 5, lid = tid & 31;
    const int m0 = blockIdx.y * TM, n0 = blockIdx.x * TN;
    const int wm = wid & 1, wn = wid >> 1;

    const int grow = tid >> 1;
    const int half = tid & 1;
    const uint4* rAh = reinterpret_cast<const uint4*>(Ah + (size_t)(m0 + grow) * K);
    const uint4* rAl = reinterpret_cast<const uint4*>(Al + (size_t)(m0 + grow) * K);
    const uint4* rBh = reinterpret_cast<const uint4*>(Bh + (size_t)(n0 + grow) * K);
    const uint4* rBl = reinterpret_cast<const uint4*>(Bl + (size_t)(n0 + grow) * K);

    uint32_t soff[4];
    #pragma unroll
    for (int j = 0; j < 4; j++)
        soff[j] = SWZ128((uint32_t)(grow * 128 + half * 64 + j * 16));

    float c[4][4][4];
    #pragma unroll
    for (int mt = 0; mt < 4; mt++)
        #pragma unroll
        for (int nt = 0; nt < 4; nt++)
            #pragma unroll
            for (int e = 0; e < 4; e++) c[mt][nt][e] = 0.f;

    const int arow = wm * 64 + (lid & 15);
    const int aq   = lid >> 4;
    const int brow = wn * 32 + (lid & 7);
    const int bq   = (lid >> 3) & 1;

    // prologue: chunk 0 -> stage 0
    {
        const int base = half * 4;
        #pragma unroll
        for (int j = 0; j < 4; j++) {
            cpa16(sb + SM_AH + soff[j], rAh + base + j);
            cpa16(sb + SM_AL + soff[j], rAl + base + j);
            cpa16(sb + SM_BH + soff[j], rBh + base + j);
            cpa16(sb + SM_BL + soff[j], rBl + base + j);
        }
        CPA_COMMIT();
    }

    const int nch = K / TKC;
    for (int ch = 0; ch < nch; ch++) {
        const uint32_t scur = sb + (uint32_t)(ch & 1) * STG_B;
        CPA_WAIT0();        // chunk ch complete (only pending group)
        __syncthreads();    // all threads done with prev stage reads + data visible
        if (ch + 1 < nch) { // prefetch ch+1 into other stage (safe: post-barrier)
            const uint32_t snxt = sb + (uint32_t)((ch + 1) & 1) * STG_B;
            const int base = (ch + 1) * (TKC / 8) + half * 4;
            #pragma unroll
            for (int j = 0; j < 4; j++) {
                cpa16(snxt + SM_AH + soff[j], rAh + base + j);
                cpa16(snxt + SM_AL + soff[j], rAl + base + j);
                cpa16(snxt + SM_BH + soff[j], rBh + base + j);
                cpa16(snxt + SM_BL + soff[j], rBl + base + j);
            }
            CPA_COMMIT();
        }

        #pragma unroll
        for (int ks = 0; ks < 4; ks++) {
            uint32_t ah[4][4], al[4][4], bh[4][2], bl[4][2];
            #pragma unroll
            for (int mt = 0; mt < 4; mt++) {
                const uint32_t off = SWZ128((uint32_t)((arow + mt * 16) * 128 + (ks * 2 + aq) * 16));
                ldmx4(ah[mt], scur + SM_AH + off);
                ldmx4(al[mt], scur + SM_AL + off);
            }
            #pragma unroll
            for (int nt = 0; nt < 4; nt++) {
                const uint32_t off = SWZ128((uint32_t)((brow + nt * 8) * 128 + (ks * 2 + bq) * 16));
                ldmx2(bh[nt], scur + SM_BH + off);
                ldmx2(bl[nt], scur + SM_BL + off);
            }
            #pragma unroll
            for (int mt = 0; mt < 4; mt++)
                #pragma unroll
                for (int nt = 0; nt < 4; nt++) {
                    mma16816(c[mt][nt], ah[mt], bh[nt]);
                    mma16816(c[mt][nt], ah[mt], bl[nt]);
                    mma16816(c[mt][nt], al[mt], bh[nt]);
                }
        }
    }

    const int mbase = m0 + wm * 64 + (lid >> 2);
    const int nbase = n0 + wn * 32 + (lid & 3) * 2;
    #pragma unroll
    for (int mt = 0; mt < 4; mt++)
        #pragma unroll
        for (int nt = 0; nt < 4; nt++) {
            float* p0 = C + (size_t)(mbase + mt * 16) * ldc + nbase + nt * 8;
            float* p1 = p0 + 8 * ldc;
            *reinterpret_cast<float2*>(p0) = make_float2(c[mt][nt][0], c[mt][nt][1]);
            *reinterpret_cast<float2*>(p1) = make_float2(c[mt][nt][2], c[mt][nt][3]);
        }
}

// ---------------- fp32 -> (hi,lo) bf16 conversions ----------------
__global__ __launch_bounds__(256)
void cvt_pair_k(const float* __restrict__ x, bf16* __restrict__ h,
                bf16* __restrict__ l, size_t n)
{
    const size_t i = (size_t)blockIdx.x * 256 + threadIdx.x;
    if (i >= n) return;
    const float v = x[i];
    const bf16 hh = __float2bfloat16(v);
    h[i] = hh;
    l[i] = __float2bfloat16(v - __bfloat162float(hh));
}

__global__ __launch_bounds__(256)
void cvt_pad_k(const float* __restrict__ x, bf16* __restrict__ h,
               bf16* __restrict__ l, int rows, int cols, int padrows)
{
    const size_t i = (size_t)blockIdx.x * 256 + threadIdx.x;
    if (i >= (size_t)padrows * cols) return;
    const int r = (int)(i / cols);
    const float v = (r < rows) ? x[i] : 0.f;
    const bf16 hh = __float2bfloat16(v);
    h[i] = hh;
    l[i] = __float2bfloat16(v - __bfloat162float(hh));
}

// ---------------- RMSNorm -> (hi,lo) bf16 ----------------
__global__ __launch_bounds__(256)
void rmsnorm_pair_k(const float* __restrict__ x, const float* __restrict__ w,
                    bf16* __restrict__ yh, bf16* __restrict__ yl,
                    int n, int in_stride)
{
    const int row = blockIdx.x;
    const float* xr = x + (size_t)row * in_stride;
    bf16* yhr = yh + (size_t)row * n;
    bf16* ylr = yl + (size_t)row * n;
    __shared__ float red[256];
    float s = 0.f;
    for (int i = threadIdx.x; i < n; i += 256) { float v = xr[i]; s += v * v; }
    red[threadIdx.x] = s; __syncthreads();
    for (int o = 128; o; o >>= 1) {
        if (threadIdx.x < o) red[threadIdx.x] += red[threadIdx.x + o];
        __syncthreads();
    }
    const float r = rsqrtf(red[0] / n + 1e-6f);
    for (int i = threadIdx.x; i < n; i += 256) {
        const float v = xr[i] * r * w[i];
        const bf16 hh = __float2bfloat16(v);
        yhr[i] = hh;
        ylr[i] = __float2bfloat16(v - __bfloat162float(hh));
    }
}

// ------- build Q (RoPE + scale) -> bf16 hi/lo [b,h,s,192] -------
__global__ __launch_bounds__(128)
void build_q_k(const float* __restrict__ q, const int* __restrict__ pos,
               bf16* __restrict__ Qhh, bf16* __restrict__ Qhl, float scale)
{
    const int s = blockIdx.x, h = blockIdx.y, b = blockIdx.z;
    const float* in = q + ((size_t)(b * SS + s)) * QBOUT + h * DQ;
    const size_t ob = (((size_t)(b * NH + h) * SS) + s) * DQ;
    const int t = threadIdx.x;
    {
        const float v = in[t] * scale;
        const bf16 hh = __float2bfloat16(v);
        Qhh[ob + t] = hh;
        Qhl[ob + t] = __float2bfloat16(v - __bfloat162float(hh));
    }
    if (t < 32) {
        const float tp = (float)pos[b * SS + s];
        const float f = exp2f((float)t * (-13.2877123795494f / 32.f));
        float c, sn; sincosf(tp * f, &sn, &c);
        const float x0 = in[DNOPE + 2 * t];
        const float x1 = in[DNOPE + 2 * t + 1];
        const float v0 = (x0 * c - x1 * sn) * scale;
        const float v1 = (x1 * c + x0 * sn) * scale;
        bf16 h0 = __float2bfloat16(v0), h1 = __float2bfloat16(v1);
        Qhh[ob + DNOPE + t]      = h0;
        Qhl[ob + DNOPE + t]      = __float2bfloat16(v0 - __bfloat162float(h0));
        Qhh[ob + DNOPE + 32 + t] = h1;
        Qhl[ob + DNOPE + 32 + t] = __float2bfloat16(v1 - __bfloat162float(h1));
    }
}

// ------- build K,V -> bf16 hi/lo [b,h,s,*] (ckv = g_c1 + QRANK, stride W1R) -------
__global__ __launch_bounds__(256)
void build_kv_k(const float* __restrict__ ckv, const float* __restrict__ kv,
                const int* __restrict__ pos,
                bf16* __restrict__ Khh, bf16* __restrict__ Khl,
                bf16* __restrict__ Vhh, bf16* __restrict__ Vhl)
{
    const int s = blockIdx.x, b = blockIdx.y;
    const size_t bs = (size_t)b * SS + s;
    __shared__ float kr[DROPE];
    const int tid = threadIdx.x;
    if (tid < 32) {
        const float tp = (float)pos[bs];
        const float f = exp2f((float)tid * (-13.2877123795494f / 32.f));
        float c, sn; sincosf(tp * f, &sn, &c);
        const float x0 = ckv[bs * W1R + KVRANK + 2 * tid];
        const float x1 = ckv[bs * W1R + KVRANK + 2 * tid + 1];
        kr[tid]      = x0 * c - x1 * sn;
        kr[32 + tid] = x1 * c + x0 * sn;
    }
    __syncthreads();
    const float* kvrow = kv + bs * KVBOUT;
    for (int idx = tid; idx < NH * DQ; idx += 256) {
        const int h = idx / DQ, d = idx % DQ;
        const float v = (d < DNOPE) ? kvrow[h * (DNOPE + DV) + d] : kr[d - DNOPE];
        const size_t o = (((size_t)(b * NH + h) * SS) + s) * DQ + d;
        const bf16 hh = __float2bfloat16(v);
        Khh[o] = hh;
        Khl[o] = __float2bfloat16(v - __bfloat162float(hh));
    }
    for (int idx = tid; idx < NH * DV; idx += 256) {
        const int h = idx / DV, d = idx % DV;
        const float v = kvrow[h * (DNOPE + DV) + DNOPE + d];
        const size_t o = (((size_t)(b * NH + h) * SS) + s) * DV + d;
        const bf16 hh = __float2bfloat16(v);
        Vhh[o] = hh;
        Vhl[o] = __float2bfloat16(v - __bfloat162float(hh));
    }
}

// ====== HMMA flash attention, cp.async pipelined K (2-stage) + early V ======
#define FQM 128
#define FKN 64
#define FQH0 0                 // Q hi: 3 panels x 16384
#define FQL0 49152             // Q lo
#define FKS0 98304             // K stages: [hi 3x8192 | lo 3x8192] = 49152 each
#define FKSTG 49152
#define FVH0 196608            // V hi 16384 (64 x 256B swizzled)
#define FVL0 212992            // V lo
#define FL_SMEM 229376

__global__ __launch_bounds__(256, 1)
void flashmma_k(const bf16* __restrict__ Qhh, const bf16* __restrict__ Qhl,
                const bf16* __restrict__ Khh, const bf16* __restrict__ Khl,
                const bf16* __restrict__ Vhh, const bf16* __restrict__ Vhl,
                bf16* __restrict__ ath, bf16* __restrict__ atl)
{
    extern __shared__ char sm[];
    const uint32_t sb = s2u(sm);
    const int tid = threadIdx.x, w = tid >> 5, l = tid & 31;
    const int qt = blockIdx.x, bh = blockIdx.y;
    const int b = bh / NH, h = bh % NH;
    const int q0 = qt * FQM;

    // prologue: prefetch K tile 0 into stage 0 (start loads ASAP)
    {
        const uint4* Kh4 = reinterpret_cast<const uint4*>(Khh + (size_t)bh * SS * DQ);
        const uint4* Kl4 = reinterpret_cast<const uint4*>(Khl + (size_t)bh * SS * DQ);
        for (int idx = tid; idx < 64 * 24; idx += 256) {
            const int row = idx / 24, u = idx % 24;
            const int p = u >> 3, qd = u & 7;
            const uint32_t off = (uint32_t)(p * 8192) + SWZ128((uint32_t)(row * 128 + qd * 16));
            cpa16(sb + FKS0 + off,         Kh4 + row * 24 + u);
            cpa16(sb + FKS0 + 24576 + off, Kl4 + row * 24 + u);
        }
        CPA_COMMIT();
    }

    // Q tile -> smem (st.shared; visible after first in-loop barrier)
    {
        const uint4* Qh4 = reinterpret_cast<const uint4*>(Qhh + ((size_t)bh * SS + q0) * DQ);
        const uint4* Ql4 = reinterpret_cast<const uint4*>(Qhl + ((size_t)bh * SS + q0) * DQ);
        for (int idx = tid; idx < 128 * 24; idx += 256) {
            const int row = idx / 24, u = idx % 24;
            const int p = u >> 3, qd = u & 7;
            const uint32_t off = (uint32_t)(p * 16384) + SWZ128((uint32_t)(row * 128 + qd * 16));
            *reinterpret_cast<uint4*>(sm + FQH0 + off) = Qh4[row * 24 + u];
            *reinterpret_cast<uint4*>(sm + FQL0 + off) = Ql4[row * 24 + u];
        }
    }

    float oacc[16][4];
    #pragma unroll
    for (int i = 0; i < 16; i++)
        #pragma unroll
        for (int e = 0; e < 4; e++) oacc[i][e] = 0.f;
    float mrow[2] = {-1e30f, -1e30f};
    float lsum[2] = {0.f, 0.f};

    const int r0 = q0 + w * 16 + (l >> 2);
    const int r1 = r0 + 8;

    const int ktmax = 2 * qt + 1;
    for (int kt = 0; kt <= ktmax; kt++) {
        const int k0 = kt * FKN;
        const uint32_t kcur = sb + FKS0 + (uint32_t)(kt & 1) * FKSTG;

        // issue V(kt) + prefetch K(kt+1); one group
        {
            const uint4* Vh4 = reinterpret_cast<const uint4*>(Vhh + ((size_t)bh * SS + k0) * DV);
            const uint4* Vl4 = reinterpret_cast<const uint4*>(Vhl + ((size_t)bh * SS + k0) * DV);
            for (int idx = tid; idx < 64 * 16; idx += 256) {
                const int row = idx >> 4, qd = idx & 15;
                const uint32_t off = SWZV((uint32_t)(row * 256 + qd * 16));
                cpa16(sb + FVH0 + off, Vh4 + row * 16 + qd);
                cpa16(sb + FVL0 + off, Vl4 + row * 16 + qd);
            }
            if (kt < ktmax) {
                const uint32_t knxt = sb + FKS0 + (uint32_t)((kt + 1) & 1) * FKSTG;
                const uint4* Kh4 = reinterpret_cast<const uint4*>(Khh + ((size_t)bh * SS + k0 + FKN) * DQ);
                const uint4* Kl4 = reinterpret_cast<const uint4*>(Khl + ((size_t)bh * SS + k0 + FKN) * DQ);
                for (int idx = tid; idx < 64 * 24; idx += 256) {
                    const int row = idx / 24, u = idx % 24;
                    const int p = u >> 3, qd = u & 7;
                    const uint32_t off = (uint32_t)(p * 8192) + SWZ128((uint32_t)(row * 128 + qd * 16));
                    cpa16(knxt + off,         Kh4 + row * 24 + u);
                    cpa16(knxt + 24576 + off, Kl4 + row * 24 + u);
                }
            }
            CPA_COMMIT();
        }
        CPA_WAIT1();        // K(kt) ready (prev group drained)
        __syncthreads();

        // ---- S = Q @ K^T (split-bf16, fp32 accum) ----
        float sacc[8][4];
        #pragma unroll
        for (int nt = 0; nt < 8; nt++)
            #pragma unroll
            for (int e = 0; e < 4; e++) sacc[nt][e] = 0.f;

        #pragma unroll
        for (int p = 0; p < 3; p++)
            #pragma unroll
            for (int ks = 0; ks < 4; ks++) {
                uint32_t ah[4], al[4];
                const uint32_t aoff = (uint32_t)(p * 16384) +
                    SWZ128((uint32_t)((w * 16 + (l & 15)) * 128 + (ks * 2 + (l >> 4)) * 16));
                ldmx4(ah, sb + FQH0 + aoff);
                ldmx4(al, sb + FQL0 + aoff);
                #pragma unroll
                for (int nt = 0; nt < 8; nt++) {
                    uint32_t bh_[2], bl_[2];
                    const uint32_t boff = (uint32_t)(p * 8192) +
                        SWZ128((uint32_t)((nt * 8 + (l & 7)) * 128 + (ks * 2 + ((l >> 3) & 1)) * 16));
                    ldmx2(bh_, kcur + boff);
                    ldmx2(bl_, kcur + 24576 + boff);
                    mma16816(sacc[nt], ah, bh_);
                    mma16816(sacc[nt], ah, bl_);
                    mma16816(sacc[nt], al, bh_);
                }
            }

        if (kt >= 2 * qt) {
            #pragma unroll
            for (int nt = 0; nt < 8; nt++) {
                const int c0 = k0 + nt * 8 + (l & 3) * 2;
                if (c0     > r0) sacc[nt][0] = -1e30f;
                if (c0 + 1 > r0) sacc[nt][1] = -1e30f;
                if (c0     > r1) sacc[nt][2] = -1e30f;
                if (c0 + 1 > r1) sacc[nt][3] = -1e30f;
            }
        }

        float alpha[2];
        #pragma unroll
        for (int sub = 0; sub < 2; sub++) {
            float tm = -1e30f;
            #pragma unroll
            for (int nt = 0; nt < 8; nt++)
                tm = fmaxf(tm, fmaxf(sacc[nt][2 * sub], sacc[nt][2 * sub + 1]));
            tm = fmaxf(tm, __shfl_xor_sync(0xffffffffu, tm, 1));
            tm = fmaxf(tm, __shfl_xor_sync(0xffffffffu, tm, 2));
            const float mn = fmaxf(mrow[sub], tm);
            alpha[sub] = __expf(mrow[sub] - mn);
            float rs = 0.f;
            #pragma unroll
            for (int nt = 0; nt < 8; nt++) {
                sacc[nt][2 * sub]     = __expf(sacc[nt][2 * sub] - mn);
                sacc[nt][2 * sub + 1] = __expf(sacc[nt][2 * sub + 1] - mn);
                rs += sacc[nt][2 * sub] + sacc[nt][2 * sub + 1];
            }
            rs += __shfl_xor_sync(0xffffffffu, rs, 1);
            rs += __shfl_xor_sync(0xffffffffu, rs, 2);
            lsum[sub] = lsum[sub] * alpha[sub] + rs;
            mrow[sub] = mn;
        }
        #pragma unroll
        for (int ntv = 0; ntv < 16; ntv++) {
            oacc[ntv][0] *= alpha[0]; oacc[ntv][1] *= alpha[0];
            oacc[ntv][2] *= alpha[1]; oacc[ntv][3] *= alpha[1];
        }

        CPA_WAIT0();        // V(kt) (+K(kt+1)) loaded
        __syncthreads();

        #pragma unroll
        for (int kt4 = 0; kt4 < 4; kt4++) {
            uint32_t pah[4], pal[4];
            {
                const float* s0 = sacc[2 * kt4];
                const float* s1 = sacc[2 * kt4 + 1];
                float h00 = __bfloat162float(__float2bfloat16(s0[0]));
                float h01 = __bfloat162float(__float2bfloat16(s0[1]));
                float h02 = __bfloat162float(__float2bfloat16(s0[2]));
                float h03 = __bfloat162float(__float2bfloat16(s0[3]));
                float h10 = __bfloat162float(__float2bfloat16(s1[0]));
                float h11 = __bfloat162float(__float2bfloat16(s1[1]));
                float h12 = __bfloat162float(__float2bfloat16(s1[2]));
                float h13 = __bfloat162float(__float2bfloat16(s1[3]));
                pah[0] = packbf2(h00, h01); pah[1] = packbf2(h02, h03);
                pah[2] = packbf2(h10, h11); pah[3] = packbf2(h12, h13);
                pal[0] = packbf2(s0[0] - h00, s0[1] - h01);
                pal[1] = packbf2(s0[2] - h02, s0[3] - h03);
                pal[2] = packbf2(s1[0] - h10, s1[1] - h11);
                pal[3] = packbf2(s1[2] - h12, s1[3] - h13);
            }
            #pragma unroll
            for (int ntv = 0; ntv < 16; ntv++) {
                uint32_t bvh[2], bvl[2];
                const uint32_t voff =
                    SWZV((uint32_t)((kt4 * 16 + (l & 7) + ((l >> 3) & 1) * 8) * 256 + ntv * 16));
                ldmx2t(bvh, sb + FVH0 + voff);
                ldmx2t(bvl, sb + FVL0 + voff);
                mma16816(oacc[ntv], pah, bvh);
                mma16816(oacc[ntv], pah, bvl);
                mma16816(oacc[ntv], pal, bvh);
            }
        }
        __syncthreads();    // protect V buf + K stage before next iter's cp.async
    }

    const float inv0 = 1.f / lsum[0];
    const float inv1 = 1.f / lsum[1];
    const size_t row0 = (size_t)(b * SS + r0) * ODIM + h * DV;
    const size_t row1 = (size_t)(b * SS + r1) * ODIM + h * DV;
    #pragma unroll
    for (int ntv = 0; ntv < 16; ntv++) {
        const int col = ntv * 8 + (l & 3) * 2;
        const float v00 = oacc[ntv][0] * inv0, v01 = oacc[ntv][1] * inv0;
        const float v10 = oacc[ntv][2] * inv1, v11 = oacc[ntv][3] * inv1;
        float h00 = __bfloat162float(__float2bfloat16(v00));
        float h01 = __bfloat162float(__float2bfloat16(v01));
        float h10 = __bfloat162float(__float2bfloat16(v10));
        float h11 = __bfloat162float(__float2bfloat16(v11));
        *reinterpret_cast<uint32_t*>(&ath[row0 + col]) = packbf2(h00, h01);
        *reinterpret_cast<uint32_t*>(&atl[row0 + col]) = packbf2(v00 - h00, v01 - h01);
        *reinterpret_cast<uint32_t*>(&ath[row1 + col]) = packbf2(h10, h11);
        *reinterpret_cast<uint32_t*>(&atl[row1 + col]) = packbf2(v10 - h10, v11 - h11);
    }
}

// ---------------- launch ----------------
extern "C" void kernel_launch(void* const* d_in, const int* in_sizes, int n_in,
                              void* d_out, int out_size)
{
    const float* hidden = (const float*)d_in[0];
    const float* qaw    = (const float*)d_in[1];
    const float* qaln   = (const float*)d_in[2];
    const float* qbw    = (const float*)d_in[3];
    const float* kvaw   = (const float*)d_in[4];
    const float* kvaln  = (const float*)d_in[5];
    const float* kvbw   = (const float*)d_in[6];
    const float* ow     = (const float*)d_in[7];
    const int*   pos    = (const int*)d_in[8];
    // d_in[9] = attention_mask (causal tril) — enforced analytically in flash kernel
    float* out = (float*)d_out;

    float *c1, *q, *kv;
    bf16 *hidh, *hidl, *w1h, *w1l, *qbwh, *qbwl, *kvbwh, *kvbwl;
    bf16 *owh, *owl, *qch, *qcl, *cnh, *cnl, *ath, *atl;
    bf16 *Qhh, *Qhl, *Khh, *Khl, *Vhh, *Vhl;
    cudaGetSymbolAddress((void**)&c1,  g_c1);   cudaGetSymbolAddress((void**)&q,    g_q);
    cudaGetSymbolAddress((void**)&kv,  g_kv);
    cudaGetSymbolAddress((void**)&hidh, g_hidh); cudaGetSymbolAddress((void**)&hidl, g_hidl);
    cudaGetSymbolAddress((void**)&w1h, g_w1h);   cudaGetSymbolAddress((void**)&w1l, g_w1l);
    cudaGetSymbolAddress((void**)&qbwh, g_qbwh); cudaGetSymbolAddress((void**)&qbwl, g_qbwl);
    cudaGetSymbolAddress((void**)&kvbwh, g_kvbwh); cudaGetSymbolAddress((void**)&kvbwl, g_kvbwl);
    cudaGetSymbolAddress((void**)&owh, g_owh);   cudaGetSymbolAddress((void**)&owl, g_owl);
    cudaGetSymbolAddress((void**)&qch, g_qch);   cudaGetSymbolAddress((void**)&qcl, g_qcl);
    cudaGetSymbolAddress((void**)&cnh, g_cnh);   cudaGetSymbolAddress((void**)&cnl, g_cnl);
    cudaGetSymbolAddress((void**)&ath, g_ath);   cudaGetSymbolAddress((void**)&atl, g_atl);
    cudaGetSymbolAddress((void**)&Qhh, g_Qhh);   cudaGetSymbolAddress((void**)&Qhl, g_Qhl);
    cudaGetSymbolAddress((void**)&Khh, g_Khh);   cudaGetSymbolAddress((void**)&Khl, g_Khl);
    cudaGetSymbolAddress((void**)&Vhh, g_Vhh);   cudaGetSymbolAddress((void**)&Vhl, g_Vhl);

    cudaFuncSetAttribute(gemm_tc,    cudaFuncAttributeMaxDynamicSharedMemorySize, GEMM_SMEM);
    cudaFuncSetAttribute(flashmma_k, cudaFuncAttributeMaxDynamicSharedMemorySize, FL_SMEM);

    #define CVT(x, h, l, n) cvt_pair_k<<<(unsigned)(((size_t)(n) + 255) / 256), 256>>>(x, h, l, (size_t)(n))
    CVT(hidden, hidh, hidl, (size_t)MTOK * HID);
    CVT(qaw,    w1h,  w1l,  (size_t)QRANK * HID);            // rows [0, 1536)
    cvt_pad_k<<<(unsigned)(((size_t)KVAPAD * HID + 255) / 256), 256>>>(
        kvaw, w1h + (size_t)QRANK * HID, w1l + (size_t)QRANK * HID,
        KVAOUT, HID, KVAPAD);                                 // rows [1536, 2176)
    CVT(qbw,    qbwh, qbwl, (size_t)QBOUT * QRANK);
    CVT(kvbw,   kvbwh, kvbwl, (size_t)KVBOUT * KVRANK);
    CVT(ow,     owh,  owl,  (size_t)HID * ODIM);

    // 1) combined [q_c | ckv] = hidden @ [q_a ; kv_a]^T   [4096, 2176]
    gemm_tc<<<dim3(W1R/TN, MTOK/TM), 256, GEMM_SMEM>>>(hidh, hidl, w1h, w1l, c1, HID, W1R);
    // 2) rmsnorm(q_c) and rmsnorm(ckv[:, :512])
    rmsnorm_pair_k<<<MTOK, 256>>>(c1, qaln, qch, qcl, QRANK, W1R);
    rmsnorm_pair_k<<<MTOK, 256>>>(c1 + QRANK, kvaln, cnh, cnl, KVRANK, W1R);
    // 3) q = qcn @ q_b^T
    gemm_tc<<<dim3(QBOUT/TN, MTOK/TM), 256, GEMM_SMEM>>>(qch, qcl, qbwh, qbwl, q, QRANK, QBOUT);
    // 4) kv = cn @ kv_b^T
    gemm_tc<<<dim3(KVBOUT/TN, MTOK/TM), 256, GEMM_SMEM>>>(cnh, cnl, kvbwh, kvbwl, kv, KVRANK, KVBOUT);
    // 5) build bf16 split Q (rope+scale) and K,V
    build_q_k<<<dim3(SS, NH, BB), 128>>>(q, pos, Qhh, Qhl, rsqrtf((float)DQ));
    build_kv_k<<<dim3(SS, BB), 256>>>(c1 + QRANK, kv, pos, Khh, Khl, Vhh, Vhl);
    // 6) HMMA flash attention -> attn (hi,lo) bf16
    flashmma_k<<<dim3(SS/FQM, BB*NH), 256, FL_SMEM>>>(Qhh, Qhl, Khh, Khl, Vhh, Vhl, ath, atl);
    // 7) out = attn @ o^T
    gemm_tc<<<dim3(HID/TN, MTOK/TM), 256, GEMM_SMEM>>>(ath, atl, owh, owl, out, ODIM, HID);
}